// round 8
// baseline (speedup 1.0000x reference)
#include <cuda_runtime.h>
#include <cuda_fp16.h>
#include <math.h>

#define Pn 128
#define Ln 512
#define En 256
#define Fn 128
#define Tn 509
#define SROW 136   // halves per smem row (272 B: ldmatrix conflict-free)

// ---------------- scratch (device globals; allocation is forbidden) ----------
__device__ __half  g_emb[(size_t)Pn * Ln * En];    // fp16 embedded tokens [p][l][e]
__device__ __half  g_conv[(size_t)Pn * 510 * Fn];  // conv+relu output [p][t'][f]
__device__ __half  g_gxh[(size_t)Pn * Tn * 1024];  // input gates fp16 [p*T][fwd512|bwd512]
__device__ float   g_ctx[Pn * En];                 // BiLSTM context [p][2H]
__device__ __half  g_cwh[Fn * 768];                // conv weights [f][w*256+e] fp16
__device__ float   g_d1wT[512 * 256];              // d1_w transposed [k][e]
__device__ __half  g_wh [1024 * 128];              // W_ih fp16 [n(fwd512|bwd512)][k]
__device__ float   g_bias[1024];                   // combined b_ih + b_hh
__device__ float   g_score[Pn];
__device__ float   g_u[En];

// ---------------- helpers ----------------------------------------------------
__device__ __forceinline__ float sigf(float x) {
    return __fdividef(1.f, 1.f + __expf(-x));
}
__device__ __forceinline__ float tanh_(float x) {
    return __fdividef(2.f, 1.f + __expf(-2.f * x)) - 1.f;
}
// HW tanh (sm_75+), ~5e-4 abs err — used only inside the LSTM recurrence
__device__ __forceinline__ float tanha(float x) {
    float y;
    asm("tanh.approx.f32 %0, %1;" : "=f"(y) : "f"(x));
    return y;
}
__device__ __forceinline__ float siga(float x) {
    return fmaf(0.5f, tanha(0.5f * x), 0.5f);
}
union UH2 { unsigned int u; __half2 h; };
__device__ __forceinline__ unsigned h2u(__half2 h) { UH2 v; v.h = h; return v.u; }
__device__ __forceinline__ __half2 u2h(unsigned x) { UH2 v; v.u = x; return v.h; }

__device__ __forceinline__ void ldm_x4(unsigned& r0, unsigned& r1, unsigned& r2, unsigned& r3,
                                       unsigned addr) {
    asm volatile("ldmatrix.sync.aligned.m8n8.x4.shared.b16 {%0,%1,%2,%3}, [%4];"
                 : "=r"(r0), "=r"(r1), "=r"(r2), "=r"(r3) : "r"(addr));
}
__device__ __forceinline__ void mma16816(float* c, const unsigned* a, unsigned b0, unsigned b1) {
    asm volatile("mma.sync.aligned.m16n8k16.row.col.f32.f16.f16.f32 "
                 "{%0,%1,%2,%3}, {%4,%5,%6,%7}, {%8,%9}, {%0,%1,%2,%3};"
                 : "+f"(c[0]), "+f"(c[1]), "+f"(c[2]), "+f"(c[3])
                 : "r"(a[0]), "r"(a[1]), "r"(a[2]), "r"(a[3]), "r"(b0), "r"(b1));
}
// fp16-accumulate variant (LSTM recurrence only)
__device__ __forceinline__ void mma16816h(unsigned* c, const unsigned* a, unsigned b0, unsigned b1) {
    asm volatile("mma.sync.aligned.m16n8k16.row.col.f16.f16.f16.f16 "
                 "{%0,%1}, {%2,%3,%4,%5}, {%6,%7}, {%0,%1};"
                 : "+r"(c[0]), "+r"(c[1])
                 : "r"(a[0]), "r"(a[1]), "r"(a[2]), "r"(a[3]), "r"(b0), "r"(b1));
}

// ---------------- launch 1: setup (prep + init_u + embed fused) ---------------
#define PREP_BLKS 1412
__global__ void __launch_bounds__(256) setup_kernel(
        const int* __restrict__ path, const int* __restrict__ query,
        const float* __restrict__ embA, const float* __restrict__ embB,
        const float* __restrict__ conv_w, const float* __restrict__ d1w,
        const float* __restrict__ wihf, const float* __restrict__ wihb,
        const float* __restrict__ bihf, const float* __restrict__ bhhf,
        const float* __restrict__ bihb, const float* __restrict__ bhhb) {
    int bx = blockIdx.x;
    if (bx < PREP_BLKS) {
        int idx = bx * 256 + threadIdx.x;
        if (idx < 98304) {                        // cwh[f][w*256+e] = conv_w[f][e][w]
            int f = idx / 768, r = idx - f * 768;
            int w = r >> 8, e = r & 255;
            g_cwh[idx] = __float2half(conv_w[(size_t)f * 768 + e * 3 + w]);
        } else if (idx < 98304 + 131072) {        // d1wT[k*256+e]
            int j = idx - 98304;
            int e = j & 255, k = j >> 8;
            g_d1wT[j] = d1w[(size_t)e * 512 + k];
        } else if (idx < 229376 + 131072) {       // g_wh[n][k] fp16
            int j = idx - 229376;
            int k = j & 127, n = j >> 7;
            float w = (n < 512) ? wihf[(size_t)n * 128 + k] : wihb[(size_t)(n - 512) * 128 + k];
            g_wh[j] = __float2half(w);
        } else if (idx < 360448 + 1024) {         // g_bias[n]
            int n = idx - 360448;
            g_bias[n] = (n < 512) ? (bihf[n] + bhhf[n]) : (bihb[n - 512] + bhhb[n - 512]);
        }
    } else if (bx < PREP_BLKS + 32768) {          // embedding gather
        int b = bx - PREP_BLKS;
        int p = b >> 8;
        int l = (b & 255) * 2 + (threadIdx.x >> 7);
        int t = threadIdx.x & 127;
        int tok = path[p * Ln + l];
        float2 v = *(const float2*)(embA + (size_t)tok * En + 2 * t);
        *(__half2*)(g_emb + ((size_t)p * Ln + l) * En + 2 * t) = __float22half2_rn(v);
    } else {                                      // init u
        g_u[threadIdx.x] = embB[(size_t)query[0] * En + threadIdx.x];
    }
}

// ---------------- launch 2: conv as GEMM (tensor cores) -----------------------
__global__ void __launch_bounds__(256) convgemm_kernel(const float* __restrict__ conv_b) {
    extern __shared__ __half smh[];
    __half* As = smh;                 // [128 m][SROW]
    __half* Bs = smh + 128 * SROW;    // [128 f][SROW]
    __shared__ float bias_s[128];

    int row0 = blockIdx.x * 128;
    int tid  = threadIdx.x;
    int wid  = tid >> 5, lane = tid & 31;
    int m0 = (wid >> 2) * 64;
    int n0 = (wid & 3) * 32;

    if (tid < 128) bias_s[tid] = conv_b[tid];

    unsigned sbase = (unsigned)__cvta_generic_to_shared(smh);
    unsigned aAddr[4], bAddr[2];
#pragma unroll
    for (int mi = 0; mi < 4; mi++) {
        int r = m0 + mi * 16 + (lane & 15);
        int ch = (lane >> 4) * 8;
        aAddr[mi] = sbase + (r * SROW + ch) * 2;
    }
#pragma unroll
    for (int bj = 0; bj < 2; bj++) {
        int r = n0 + bj * 16 + (lane & 7) + ((lane >> 4) << 3);
        int ch = ((lane >> 3) & 1) * 8;
        bAddr[bj] = sbase + (128 * SROW + r * SROW + ch) * 2;
    }

    float acc[4][4][4];
#pragma unroll
    for (int mi = 0; mi < 4; mi++)
#pragma unroll
        for (int nj = 0; nj < 4; nj++)
#pragma unroll
            for (int q = 0; q < 4; q++) acc[mi][nj][q] = 0.f;

    for (int kt = 0; kt < 6; kt++) {
        int k0 = kt * 128;
        if (kt) __syncthreads();
        for (int idx = tid; idx < 2048; idx += 256) {
            int rr = idx >> 4, c = idx & 15;
            int gr = row0 + rr;
            int p = gr / 510, t = gr - p * 510;
            const uint4* asrc = (const uint4*)(g_emb + ((size_t)p * Ln + t) * En + k0);
            *(uint4*)(As + rr * SROW + c * 8) = asrc[c];
            const uint4* bsrc = (const uint4*)(g_cwh + (size_t)rr * 768 + k0);
            *(uint4*)(Bs + rr * SROW + c * 8) = bsrc[c];
        }
        __syncthreads();

#pragma unroll
        for (int ks = 0; ks < 8; ks++) {
            unsigned a[4][4], b[2][4];
#pragma unroll
            for (int mi = 0; mi < 4; mi++)
                ldm_x4(a[mi][0], a[mi][1], a[mi][2], a[mi][3], aAddr[mi] + ks * 32);
#pragma unroll
            for (int bj = 0; bj < 2; bj++)
                ldm_x4(b[bj][0], b[bj][1], b[bj][2], b[bj][3], bAddr[bj] + ks * 32);
#pragma unroll
            for (int mi = 0; mi < 4; mi++)
#pragma unroll
                for (int nj = 0; nj < 4; nj++)
                    mma16816(acc[mi][nj], a[mi], b[nj >> 1][(nj & 1) * 2], b[nj >> 1][(nj & 1) * 2 + 1]);
        }
    }

    int qr = lane >> 2, qc = (lane & 3) * 2;
#pragma unroll
    for (int mi = 0; mi < 4; mi++) {
#pragma unroll
        for (int nj = 0; nj < 4; nj++) {
            int cc = n0 + nj * 8 + qc;
            float bx = bias_s[cc], by = bias_s[cc + 1];
            int r1 = row0 + m0 + mi * 16 + qr;
            __half2 v0 = __floats2half2_rn(fmaxf(acc[mi][nj][0] + bx, 0.f),
                                           fmaxf(acc[mi][nj][1] + by, 0.f));
            *(__half2*)(g_conv + (size_t)r1 * 128 + cc) = v0;
            __half2 v1 = __floats2half2_rn(fmaxf(acc[mi][nj][2] + bx, 0.f),
                                           fmaxf(acc[mi][nj][3] + by, 0.f));
            *(__half2*)(g_conv + (size_t)(r1 + 8) * 128 + cc) = v1;
        }
    }
}

// ---------------- launch 3: input-gate GEMM (pool fused into A-load) ----------
__global__ void __launch_bounds__(256) gemm_kernel() {
    extern __shared__ __half smh[];
    __half* As = smh;                 // [128 m][SROW]
    __half* Bs = smh + 128 * SROW;    // [128 n][SROW]
    __shared__ float bias_s[128];

    int row0 = blockIdx.x * 128;
    int col0 = blockIdx.y * 128;
    int tid  = threadIdx.x;
    int wid  = tid >> 5, lane = tid & 31;
    int m0 = (wid >> 2) * 64;
    int n0 = (wid & 3) * 32;

    if (tid < 128) bias_s[tid] = g_bias[col0 + tid];

    {
        const uint4* bsrc = (const uint4*)(g_wh + (size_t)col0 * 128);
        for (int idx = tid; idx < 2048; idx += 256) {
            int r = idx >> 4, c = idx & 15;
            int gr = row0 + r;
            int p = gr / Tn, t = gr - p * Tn;
            const uint4* csrc = (const uint4*)(g_conv + ((size_t)p * 510 + t) * 128);
            uint4 x = csrc[c], y = csrc[c + 16];
            UH2 ax, ay, r0, r1, r2, r3;
            ax.u = x.x; ay.u = y.x; r0.h = __hmax2(ax.h, ay.h);
            ax.u = x.y; ay.u = y.y; r1.h = __hmax2(ax.h, ay.h);
            ax.u = x.z; ay.u = y.z; r2.h = __hmax2(ax.h, ay.h);
            ax.u = x.w; ay.u = y.w; r3.h = __hmax2(ax.h, ay.h);
            uint4 m4 = make_uint4(r0.u, r1.u, r2.u, r3.u);
            *(uint4*)(As + r * SROW + c * 8) = m4;
            *(uint4*)(Bs + r * SROW + c * 8) = bsrc[r * 16 + c];
        }
    }
    __syncthreads();

    unsigned sbase = (unsigned)__cvta_generic_to_shared(smh);
    unsigned aAddr[4], bAddr[2];
#pragma unroll
    for (int mi = 0; mi < 4; mi++) {
        int r = m0 + mi * 16 + (lane & 15);
        int ch = (lane >> 4) * 8;
        aAddr[mi] = sbase + (r * SROW + ch) * 2;
    }
#pragma unroll
    for (int bj = 0; bj < 2; bj++) {
        int r = n0 + bj * 16 + (lane & 7) + ((lane >> 4) << 3);
        int ch = ((lane >> 3) & 1) * 8;
        bAddr[bj] = sbase + (128 * SROW + r * SROW + ch) * 2;
    }

    float acc[4][4][4];
#pragma unroll
    for (int mi = 0; mi < 4; mi++)
#pragma unroll
        for (int nj = 0; nj < 4; nj++)
#pragma unroll
            for (int q = 0; q < 4; q++) acc[mi][nj][q] = 0.f;

#pragma unroll
    for (int ks = 0; ks < 8; ks++) {
        unsigned a[4][4], b[2][4];
#pragma unroll
        for (int mi = 0; mi < 4; mi++)
            ldm_x4(a[mi][0], a[mi][1], a[mi][2], a[mi][3], aAddr[mi] + ks * 32);
#pragma unroll
        for (int bj = 0; bj < 2; bj++)
            ldm_x4(b[bj][0], b[bj][1], b[bj][2], b[bj][3], bAddr[bj] + ks * 32);
#pragma unroll
        for (int mi = 0; mi < 4; mi++)
#pragma unroll
            for (int nj = 0; nj < 4; nj++)
                mma16816(acc[mi][nj], a[mi], b[nj >> 1][(nj & 1) * 2], b[nj >> 1][(nj & 1) * 2 + 1]);
    }

    int qr = lane >> 2, qc = (lane & 3) * 2;
#pragma unroll
    for (int mi = 0; mi < 4; mi++) {
#pragma unroll
        for (int nj = 0; nj < 4; nj++) {
            int cc = n0 + nj * 8 + qc;
            float bx = bias_s[cc], by = bias_s[cc + 1];
            size_t base = (size_t)(row0 + m0 + mi * 16 + qr) * 1024 + col0 + cc;
            *(__half2*)(g_gxh + base) = __floats2half2_rn(acc[mi][nj][0] + bx, acc[mi][nj][1] + by);
            *(__half2*)(g_gxh + base + 8 * 1024) = __floats2half2_rn(acc[mi][nj][2] + bx, acc[mi][nj][3] + by);
        }
    }
}

// ---------------- launch 4: LSTM recurrence v3 --------------------------------
// 128 CTAs: bid=(pg<<1)|dir, paths pg*2..+1; 512 threads, 16 warps.
// Gate-interleaved A rows: warp w owns units [w*8, w*8+8); tile0 = gates i/f,
// tile1 = g/o for those units. After fp16-accum MMA, lanes with (l&3)==0 hold
// all 4 gate preacts for (unit w*8+(l>>2), paths 0-1) as half2 — pointwise is
// redistributed via 4 shfls to lanes 0-15 (item = (l>>1, l&1)); no pre-smem.
// hN double-buffered -> exactly ONE __syncthreads per step.
__global__ void __launch_bounds__(512, 1) lstm_kernel(const float* __restrict__ whhf,
                                                      const float* __restrict__ whhb) {
    __shared__ __align__(16) __half hN[2][8][136];   // [buf][path-slot][unit]

    int bid = blockIdx.x;
    int dir = bid & 1;
    int pg  = bid >> 1;
    int tid = threadIdx.x;
    int w   = tid >> 5, l = tid & 31;

    const float* whh = dir ? whhb : whhf;

    // A fragments, gate-interleaved rows. unit ui = w*8 + (l>>2).
    int ui = w * 8 + (l >> 2);
    unsigned A0[8][4], A1[8][4];   // tile0: rows0-7=i, rows8-15=f; tile1: g,o
#pragma unroll
    for (int kc = 0; kc < 8; kc++) {
        int k = kc * 16 + (l & 3) * 2;
        float2 vi0 = *(const float2*)(whh + (size_t)(ui)       * 128 + k);
        float2 vf0 = *(const float2*)(whh + (size_t)(ui + 128) * 128 + k);
        float2 vi1 = *(const float2*)(whh + (size_t)(ui)       * 128 + k + 8);
        float2 vf1 = *(const float2*)(whh + (size_t)(ui + 128) * 128 + k + 8);
        A0[kc][0] = h2u(__float22half2_rn(vi0));
        A0[kc][1] = h2u(__float22half2_rn(vf0));
        A0[kc][2] = h2u(__float22half2_rn(vi1));
        A0[kc][3] = h2u(__float22half2_rn(vf1));
        float2 vg0 = *(const float2*)(whh + (size_t)(ui + 256) * 128 + k);
        float2 vo0 = *(const float2*)(whh + (size_t)(ui + 384) * 128 + k);
        float2 vg1 = *(const float2*)(whh + (size_t)(ui + 256) * 128 + k + 8);
        float2 vo1 = *(const float2*)(whh + (size_t)(ui + 384) * 128 + k + 8);
        A1[kc][0] = h2u(__float22half2_rn(vg0));
        A1[kc][1] = h2u(__float22half2_rn(vo0));
        A1[kc][2] = h2u(__float22half2_rn(vg1));
        A1[kc][3] = h2u(__float22half2_rn(vo1));
    }

    // zero both hN buffers (2*8*136 = 2176 halves = 1088 half2)
    for (int i = tid; i < 1088; i += 512) ((__half2*)&hN[0][0][0])[i] = __float2half2_rn(0.f);

    // pointwise ownership: lanes 0-15 of every warp; item (du = l>>1, p = l&1)
    bool act = l < 16;
    int du = (l & 15) >> 1, p = l & 1;
    int u  = w * 8 + du;
    int pathg = pg * 2 + p;
    long stride = dir ? -1024 : 1024;
    const __half* gp = g_gxh + (size_t)pathg * Tn * 1024 + dir * 512 + u
                     + (dir ? (size_t)(Tn - 1) * 1024 : 0);
    float gi = 0.f, gf = 0.f, gg = 0.f, go = 0.f;
    if (act) {
        gi = __half2float(gp[0]);   gf = __half2float(gp[128]);
        gg = __half2float(gp[256]); go = __half2float(gp[384]);
    }

    float c = 0.f, hval = 0.f;
    unsigned sb = (unsigned)__cvta_generic_to_shared(&hN[0][0][0]);
    unsigned ldlane = ((l & 7) * 136 + (l >> 3) * 8) * 2;
    int srcl = ((l & 15) >> 1) * 4;   // shfl source lane

    __syncthreads();

    for (int s = 0; s < Tn; s++) {
        int cb = s & 1;
        // prefetch next step's gx
        const __half* gn = gp + ((s + 1 < Tn) ? stride : 0);
        float ni = 0.f, nf = 0.f, ng = 0.f, no_ = 0.f;
        if (act) {
            ni = __half2float(gn[0]);   nf = __half2float(gn[128]);
            ng = __half2float(gn[256]); no_ = __half2float(gn[384]);
        }

        unsigned b[8][2];
        unsigned ldbase = sb + cb * (8 * 136 * 2) + ldlane;
#pragma unroll
        for (int ks = 0; ks < 4; ks++) {
            unsigned r0, r1, r2, r3;
            ldm_x4(r0, r1, r2, r3, ldbase + ks * 64);
            b[2 * ks][0] = r0;     b[2 * ks][1] = r1;
            b[2 * ks + 1][0] = r2; b[2 * ks + 1][1] = r3;
        }
        // 4 independent fp16-accum chains of 4
        unsigned C0a[2] = {0u, 0u}, C0b[2] = {0u, 0u};
        unsigned C1a[2] = {0u, 0u}, C1b[2] = {0u, 0u};
#pragma unroll
        for (int kc = 0; kc < 4; kc++) {
            mma16816h(C0a, A0[kc], b[kc][0], b[kc][1]);
            mma16816h(C1a, A1[kc], b[kc][0], b[kc][1]);
            mma16816h(C0b, A0[kc + 4], b[kc + 4][0], b[kc + 4][1]);
            mma16816h(C1b, A1[kc + 4], b[kc + 4][0], b[kc + 4][1]);
        }
        // combine: lanes (l&3)==0 now hold [i|f|g|o] for (ui, paths 0-1)
        unsigned I2 = h2u(__hadd2(u2h(C0a[0]), u2h(C0b[0])));
        unsigned F2 = h2u(__hadd2(u2h(C0a[1]), u2h(C0b[1])));
        unsigned G2 = h2u(__hadd2(u2h(C1a[0]), u2h(C1b[0])));
        unsigned O2 = h2u(__hadd2(u2h(C1a[1]), u2h(C1b[1])));
        // redistribute to lanes 0-15
        unsigned Ish = __shfl_sync(0xffffffffu, I2, srcl);
        unsigned Fsh = __shfl_sync(0xffffffffu, F2, srcl);
        unsigned Gsh = __shfl_sync(0xffffffffu, G2, srcl);
        unsigned Osh = __shfl_sync(0xffffffffu, O2, srcl);

        if (act) {
            __half2 ih = u2h(Ish), fh = u2h(Fsh), gh = u2h(Gsh), oh = u2h(Osh);
            float pi = __half2float(p ? __high2half(ih) : __low2half(ih));
            float pf = __half2float(p ? __high2half(fh) : __low2half(fh));
            float pg_ = __half2float(p ? __high2half(gh) : __low2half(gh));
            float po = __half2float(p ? __high2half(oh) : __low2half(oh));
            float iv = siga (gi + pi);
            float fv = siga (gf + pf);
            float gv = tanha(gg + pg_);
            float ov = siga (go + po);
            c = fv * c + iv * gv;
            hval = ov * tanha(c);
            hN[cb ^ 1][p][u] = __float2half(hval);
        }

        gi = ni; gf = nf; gg = ng; go = no_;
        gp = gn;
        __syncthreads();
    }
    if (act) g_ctx[pathg * 256 + dir * 128 + u] = hval;
}

// ---------------- attention --------------------------------------------------
__global__ void __launch_bounds__(256) att1_kernel(const float* __restrict__ d1b,
                                                   const float* __restrict__ d2w,
                                                   const float* __restrict__ d2b) {
    __shared__ float cat[512];
    __shared__ float red[256];
    int p = blockIdx.x, tid = threadIdx.x;
    cat[tid]       = g_ctx[p * 256 + tid];
    cat[256 + tid] = g_u[tid];
    __syncthreads();
    float acc = d1b[tid];
#pragma unroll 8
    for (int k = 0; k < 512; k++) acc += cat[k] * g_d1wT[k * 256 + tid];
    red[tid] = tanh_(acc) * d2w[tid];
    __syncthreads();
    for (int s = 128; s > 0; s >>= 1) {
        if (tid < s) red[tid] += red[tid + s];
        __syncthreads();
    }
    if (tid == 0) g_score[p] = red[0] + d2b[0];
}

__global__ void __launch_bounds__(256) att2_kernel(const float* __restrict__ d1b) {
    __shared__ float al[128];
    __shared__ float red[128];
    __shared__ float cat[512];
    int tid = threadIdx.x;
    cat[tid] = g_u[tid];
    if (tid < 128) red[tid] = g_score[tid];
    __syncthreads();
    for (int s = 64; s > 0; s >>= 1) {
        if (tid < s) red[tid] = fmaxf(red[tid], red[tid + s]);
        __syncthreads();
    }
    float m = red[0];
    __syncthreads();
    if (tid < 128) { float e = __expf(g_score[tid] - m); al[tid] = e; red[tid] = e; }
    __syncthreads();
    for (int s = 64; s > 0; s >>= 1) {
        if (tid < s) red[tid] += red[tid + s];
        __syncthreads();
    }
    float inv = __fdividef(1.f, red[0]);
    float o = 0.f;
#pragma unroll 8
    for (int p = 0; p < 128; p++) o += al[p] * g_ctx[p * 256 + tid];
    cat[256 + tid] = o * inv;
    __syncthreads();
    float acc = d1b[tid];
#pragma unroll 8
    for (int k = 0; k < 512; k++) acc += cat[k] * g_d1wT[k * 256 + tid];
    __syncthreads();
    g_u[tid] = acc;
}

__global__ void __launch_bounds__(256) final_kernel(const float* __restrict__ d2w,
                                                    const float* __restrict__ d2b,
                                                    float* __restrict__ out) {
    __shared__ float red[256];
    int tid = threadIdx.x;
    red[tid] = fmaxf(g_u[tid], 0.f) * d2w[tid];
    __syncthreads();
    for (int s = 128; s > 0; s >>= 1) {
        if (tid < s) red[tid] += red[tid + s];
        __syncthreads();
    }
    if (tid == 0) out[0] = __fdividef(1.f, 1.f + __expf(-(red[0] + d2b[0])));
}

// ---------------- launch ------------------------------------------------------
extern "C" void kernel_launch(void* const* d_in, const int* in_sizes, int n_in,
                              void* d_out, int out_size) {
    const int*   path   = (const int*)  d_in[0];
    const int*   query  = (const int*)  d_in[1];
    const float* embA   = (const float*)d_in[2];
    const float* embB   = (const float*)d_in[3];
    const float* conv_w = (const float*)d_in[4];
    const float* conv_b = (const float*)d_in[5];
    const float* wihf   = (const float*)d_in[6];
    const float* whhf   = (const float*)d_in[7];
    const float* bihf   = (const float*)d_in[8];
    const float* bhhf   = (const float*)d_in[9];
    const float* wihb   = (const float*)d_in[10];
    const float* whhb   = (const float*)d_in[11];
    const float* bihb   = (const float*)d_in[12];
    const float* bhhb   = (const float*)d_in[13];
    const float* d1w    = (const float*)d_in[14];
    const float* d1b    = (const float*)d_in[15];
    const float* d2w    = (const float*)d_in[16];
    const float* d2b    = (const float*)d_in[17];
    float* out = (float*)d_out;

    const int mma_smem = 2 * 128 * SROW * 2;           // 69632 B
    cudaFuncSetAttribute(gemm_kernel, cudaFuncAttributeMaxDynamicSharedMemorySize, mma_smem);
    cudaFuncSetAttribute(convgemm_kernel, cudaFuncAttributeMaxDynamicSharedMemorySize, mma_smem);

    setup_kernel<<<PREP_BLKS + 32768 + 1, 256>>>(path, query, embA, embB, conv_w, d1w,
                                                 wihf, wihb, bihf, bhhf, bihb, bhhb);
    convgemm_kernel<<<510, 256, mma_smem>>>(conv_b);
    gemm_kernel<<<dim3(509, 8), 256, mma_smem>>>();
    lstm_kernel<<<128, 512>>>(whhf, whhb);
    for (int it = 0; it < 2; it++) {
        att1_kernel<<<128, 256>>>(d1b, d2w, d2b);
        att2_kernel<<<1, 256>>>(d1b);
    }
    final_kernel<<<1, 256>>>(d2w, d2b, out);
}

// round 9
// speedup vs baseline: 1.2366x; 1.2366x over previous
#include <cuda_runtime.h>
#include <cuda_fp16.h>
#include <math.h>

#define Pn 128
#define Ln 512
#define En 256
#define Fn 128
#define Tn 509
#define SROW 136   // halves per smem row (272 B: ldmatrix conflict-free)

// ---------------- scratch (device globals; allocation is forbidden) ----------
__device__ __half  g_emb[(size_t)Pn * Ln * En];    // fp16 embedded tokens [p][l][e]
__device__ __half  g_conv[(size_t)Pn * 510 * Fn];  // conv+relu output [p][t'][f]
__device__ __half  g_gxh[(size_t)Pn * Tn * 1024];  // input gates fp16 [p*T][fwd512|bwd512]
__device__ float   g_ctx[Pn * En];                 // BiLSTM context [p][2H]
__device__ __half  g_cwh[Fn * 768];                // conv weights [f][w*256+e] fp16
__device__ float   g_d1wT[512 * 256];              // d1_w transposed [k][e]
__device__ __half  g_wh [1024 * 128];              // W_ih fp16 [n(fwd512|bwd512)][k]
__device__ float   g_bias[1024];                   // combined b_ih + b_hh
__device__ float   g_score[Pn];
__device__ float   g_u[En];

// ---------------- helpers ----------------------------------------------------
__device__ __forceinline__ float sigf(float x) {
    return __fdividef(1.f, 1.f + __expf(-x));
}
__device__ __forceinline__ float tanh_(float x) {
    return __fdividef(2.f, 1.f + __expf(-2.f * x)) - 1.f;
}
// HW tanh (sm_75+), ~5e-4 abs err — used only inside the LSTM recurrence
__device__ __forceinline__ float tanha(float x) {
    float y;
    asm("tanh.approx.f32 %0, %1;" : "=f"(y) : "f"(x));
    return y;
}
__device__ __forceinline__ float siga(float x) {
    return fmaf(0.5f, tanha(0.5f * x), 0.5f);
}
union UH2 { unsigned int u; __half2 h; };
__device__ __forceinline__ unsigned h2u(__half2 h) { UH2 v; v.h = h; return v.u; }
__device__ __forceinline__ __half2 u2h(unsigned x) { UH2 v; v.u = x; return v.h; }

__device__ __forceinline__ void ldm_x4(unsigned& r0, unsigned& r1, unsigned& r2, unsigned& r3,
                                       unsigned addr) {
    asm volatile("ldmatrix.sync.aligned.m8n8.x4.shared.b16 {%0,%1,%2,%3}, [%4];"
                 : "=r"(r0), "=r"(r1), "=r"(r2), "=r"(r3) : "r"(addr));
}
__device__ __forceinline__ void mma16816(float* c, const unsigned* a, unsigned b0, unsigned b1) {
    asm volatile("mma.sync.aligned.m16n8k16.row.col.f32.f16.f16.f32 "
                 "{%0,%1,%2,%3}, {%4,%5,%6,%7}, {%8,%9}, {%0,%1,%2,%3};"
                 : "+f"(c[0]), "+f"(c[1]), "+f"(c[2]), "+f"(c[3])
                 : "r"(a[0]), "r"(a[1]), "r"(a[2]), "r"(a[3]), "r"(b0), "r"(b1));
}

// ---------------- launch 1: setup (prep + init_u + embed fused) ---------------
#define PREP_BLKS 1412
__global__ void __launch_bounds__(256) setup_kernel(
        const int* __restrict__ path, const int* __restrict__ query,
        const float* __restrict__ embA, const float* __restrict__ embB,
        const float* __restrict__ conv_w, const float* __restrict__ d1w,
        const float* __restrict__ wihf, const float* __restrict__ wihb,
        const float* __restrict__ bihf, const float* __restrict__ bhhf,
        const float* __restrict__ bihb, const float* __restrict__ bhhb) {
    int bx = blockIdx.x;
    if (bx < PREP_BLKS) {
        int idx = bx * 256 + threadIdx.x;
        if (idx < 98304) {                        // cwh[f][w*256+e] = conv_w[f][e][w]
            int f = idx / 768, r = idx - f * 768;
            int w = r >> 8, e = r & 255;
            g_cwh[idx] = __float2half(conv_w[(size_t)f * 768 + e * 3 + w]);
        } else if (idx < 98304 + 131072) {        // d1wT[k*256+e]
            int j = idx - 98304;
            int e = j & 255, k = j >> 8;
            g_d1wT[j] = d1w[(size_t)e * 512 + k];
        } else if (idx < 229376 + 131072) {       // g_wh[n][k] fp16
            int j = idx - 229376;
            int k = j & 127, n = j >> 7;
            float w = (n < 512) ? wihf[(size_t)n * 128 + k] : wihb[(size_t)(n - 512) * 128 + k];
            g_wh[j] = __float2half(w);
        } else if (idx < 360448 + 1024) {         // g_bias[n]
            int n = idx - 360448;
            g_bias[n] = (n < 512) ? (bihf[n] + bhhf[n]) : (bihb[n - 512] + bhhb[n - 512]);
        }
    } else if (bx < PREP_BLKS + 32768) {          // embedding gather
        int b = bx - PREP_BLKS;
        int p = b >> 8;
        int l = (b & 255) * 2 + (threadIdx.x >> 7);
        int t = threadIdx.x & 127;
        int tok = path[p * Ln + l];
        float2 v = *(const float2*)(embA + (size_t)tok * En + 2 * t);
        *(__half2*)(g_emb + ((size_t)p * Ln + l) * En + 2 * t) = __float22half2_rn(v);
    } else {                                      // init u
        g_u[threadIdx.x] = embB[(size_t)query[0] * En + threadIdx.x];
    }
}

// ---------------- launch 2: conv as GEMM (tensor cores) -----------------------
__global__ void __launch_bounds__(256) convgemm_kernel(const float* __restrict__ conv_b) {
    extern __shared__ __half smh[];
    __half* As = smh;                 // [128 m][SROW]
    __half* Bs = smh + 128 * SROW;    // [128 f][SROW]
    __shared__ float bias_s[128];

    int row0 = blockIdx.x * 128;
    int tid  = threadIdx.x;
    int wid  = tid >> 5, lane = tid & 31;
    int m0 = (wid >> 2) * 64;
    int n0 = (wid & 3) * 32;

    if (tid < 128) bias_s[tid] = conv_b[tid];

    unsigned sbase = (unsigned)__cvta_generic_to_shared(smh);
    unsigned aAddr[4], bAddr[2];
#pragma unroll
    for (int mi = 0; mi < 4; mi++) {
        int r = m0 + mi * 16 + (lane & 15);
        int ch = (lane >> 4) * 8;
        aAddr[mi] = sbase + (r * SROW + ch) * 2;
    }
#pragma unroll
    for (int bj = 0; bj < 2; bj++) {
        int r = n0 + bj * 16 + (lane & 7) + ((lane >> 4) << 3);
        int ch = ((lane >> 3) & 1) * 8;
        bAddr[bj] = sbase + (128 * SROW + r * SROW + ch) * 2;
    }

    float acc[4][4][4];
#pragma unroll
    for (int mi = 0; mi < 4; mi++)
#pragma unroll
        for (int nj = 0; nj < 4; nj++)
#pragma unroll
            for (int q = 0; q < 4; q++) acc[mi][nj][q] = 0.f;

    for (int kt = 0; kt < 6; kt++) {
        int k0 = kt * 128;
        if (kt) __syncthreads();
        for (int idx = tid; idx < 2048; idx += 256) {
            int rr = idx >> 4, c = idx & 15;
            int gr = row0 + rr;
            int p = gr / 510, t = gr - p * 510;
            const uint4* asrc = (const uint4*)(g_emb + ((size_t)p * Ln + t) * En + k0);
            *(uint4*)(As + rr * SROW + c * 8) = asrc[c];
            const uint4* bsrc = (const uint4*)(g_cwh + (size_t)rr * 768 + k0);
            *(uint4*)(Bs + rr * SROW + c * 8) = bsrc[c];
        }
        __syncthreads();

#pragma unroll
        for (int ks = 0; ks < 8; ks++) {
            unsigned a[4][4], b[2][4];
#pragma unroll
            for (int mi = 0; mi < 4; mi++)
                ldm_x4(a[mi][0], a[mi][1], a[mi][2], a[mi][3], aAddr[mi] + ks * 32);
#pragma unroll
            for (int bj = 0; bj < 2; bj++)
                ldm_x4(b[bj][0], b[bj][1], b[bj][2], b[bj][3], bAddr[bj] + ks * 32);
#pragma unroll
            for (int mi = 0; mi < 4; mi++)
#pragma unroll
                for (int nj = 0; nj < 4; nj++)
                    mma16816(acc[mi][nj], a[mi], b[nj >> 1][(nj & 1) * 2], b[nj >> 1][(nj & 1) * 2 + 1]);
        }
    }

    int qr = lane >> 2, qc = (lane & 3) * 2;
#pragma unroll
    for (int mi = 0; mi < 4; mi++) {
#pragma unroll
        for (int nj = 0; nj < 4; nj++) {
            int cc = n0 + nj * 8 + qc;
            float bx = bias_s[cc], by = bias_s[cc + 1];
            int r1 = row0 + m0 + mi * 16 + qr;
            __half2 v0 = __floats2half2_rn(fmaxf(acc[mi][nj][0] + bx, 0.f),
                                           fmaxf(acc[mi][nj][1] + by, 0.f));
            *(__half2*)(g_conv + (size_t)r1 * 128 + cc) = v0;
            __half2 v1 = __floats2half2_rn(fmaxf(acc[mi][nj][2] + bx, 0.f),
                                           fmaxf(acc[mi][nj][3] + by, 0.f));
            *(__half2*)(g_conv + (size_t)(r1 + 8) * 128 + cc) = v1;
        }
    }
}

// ---------------- launch 3: input-gate GEMM (pool fused into A-load) ----------
__global__ void __launch_bounds__(256) gemm_kernel() {
    extern __shared__ __half smh[];
    __half* As = smh;                 // [128 m][SROW]
    __half* Bs = smh + 128 * SROW;    // [128 n][SROW]
    __shared__ float bias_s[128];

    int row0 = blockIdx.x * 128;
    int col0 = blockIdx.y * 128;
    int tid  = threadIdx.x;
    int wid  = tid >> 5, lane = tid & 31;
    int m0 = (wid >> 2) * 64;
    int n0 = (wid & 3) * 32;

    if (tid < 128) bias_s[tid] = g_bias[col0 + tid];

    {
        const uint4* bsrc = (const uint4*)(g_wh + (size_t)col0 * 128);
        for (int idx = tid; idx < 2048; idx += 256) {
            int r = idx >> 4, c = idx & 15;
            int gr = row0 + r;
            int p = gr / Tn, t = gr - p * Tn;
            const uint4* csrc = (const uint4*)(g_conv + ((size_t)p * 510 + t) * 128);
            uint4 x = csrc[c], y = csrc[c + 16];
            UH2 ax, ay, r0, r1, r2, r3;
            ax.u = x.x; ay.u = y.x; r0.h = __hmax2(ax.h, ay.h);
            ax.u = x.y; ay.u = y.y; r1.h = __hmax2(ax.h, ay.h);
            ax.u = x.z; ay.u = y.z; r2.h = __hmax2(ax.h, ay.h);
            ax.u = x.w; ay.u = y.w; r3.h = __hmax2(ax.h, ay.h);
            uint4 m4 = make_uint4(r0.u, r1.u, r2.u, r3.u);
            *(uint4*)(As + r * SROW + c * 8) = m4;
            *(uint4*)(Bs + r * SROW + c * 8) = bsrc[r * 16 + c];
        }
    }
    __syncthreads();

    unsigned sbase = (unsigned)__cvta_generic_to_shared(smh);
    unsigned aAddr[4], bAddr[2];
#pragma unroll
    for (int mi = 0; mi < 4; mi++) {
        int r = m0 + mi * 16 + (lane & 15);
        int ch = (lane >> 4) * 8;
        aAddr[mi] = sbase + (r * SROW + ch) * 2;
    }
#pragma unroll
    for (int bj = 0; bj < 2; bj++) {
        int r = n0 + bj * 16 + (lane & 7) + ((lane >> 4) << 3);
        int ch = ((lane >> 3) & 1) * 8;
        bAddr[bj] = sbase + (128 * SROW + r * SROW + ch) * 2;
    }

    float acc[4][4][4];
#pragma unroll
    for (int mi = 0; mi < 4; mi++)
#pragma unroll
        for (int nj = 0; nj < 4; nj++)
#pragma unroll
            for (int q = 0; q < 4; q++) acc[mi][nj][q] = 0.f;

#pragma unroll
    for (int ks = 0; ks < 8; ks++) {
        unsigned a[4][4], b[2][4];
#pragma unroll
        for (int mi = 0; mi < 4; mi++)
            ldm_x4(a[mi][0], a[mi][1], a[mi][2], a[mi][3], aAddr[mi] + ks * 32);
#pragma unroll
        for (int bj = 0; bj < 2; bj++)
            ldm_x4(b[bj][0], b[bj][1], b[bj][2], b[bj][3], bAddr[bj] + ks * 32);
#pragma unroll
        for (int mi = 0; mi < 4; mi++)
#pragma unroll
            for (int nj = 0; nj < 4; nj++)
                mma16816(acc[mi][nj], a[mi], b[nj >> 1][(nj & 1) * 2], b[nj >> 1][(nj & 1) * 2 + 1]);
    }

    int qr = lane >> 2, qc = (lane & 3) * 2;
#pragma unroll
    for (int mi = 0; mi < 4; mi++) {
#pragma unroll
        for (int nj = 0; nj < 4; nj++) {
            int cc = n0 + nj * 8 + qc;
            float bx = bias_s[cc], by = bias_s[cc + 1];
            size_t base = (size_t)(row0 + m0 + mi * 16 + qr) * 1024 + col0 + cc;
            *(__half2*)(g_gxh + base) = __floats2half2_rn(acc[mi][nj][0] + bx, acc[mi][nj][1] + by);
            *(__half2*)(g_gxh + base + 8 * 1024) = __floats2half2_rn(acc[mi][nj][2] + bx, acc[mi][nj][3] + by);
        }
    }
}

// ---------------- launch 4: LSTM recurrence v4 (8 warps) -----------------------
// 128 CTAs: bid=(pg<<1)|dir, paths pg*2, pg*2+1; 256 threads (8 warps).
// Warp w owns gate rows [w*64, w*64+64) = 4 m16 tiles x 8 k-chunks, A frags
// register-resident (128 regs), fp32 accum, 4 independent depth-8 MMA chains.
// Pointwise: every thread owns one (unit = tid>>1, path = tid&1).
__global__ void __launch_bounds__(256, 1) lstm_kernel(const float* __restrict__ whhf,
                                                      const float* __restrict__ whhb) {
    __shared__ float pre[512][10];               // 20 KB, conflict-free reads
    __shared__ __align__(16) __half hN[8][136];  // [path-slot][unit]; rows 2-7 zero

    int bid = blockIdx.x;
    int dir = bid & 1;
    int pg  = bid >> 1;
    int tid = threadIdx.x;
    int w   = tid >> 5, l = tid & 31;

    const float* whh = dir ? whhb : whhf;

    // A fragments: warp w owns gate-rows [w*64, w*64+64): 4 m16 tiles x 8 k-chunks
    unsigned A[4][8][4];
    int rbase = w * 64;
#pragma unroll
    for (int mt = 0; mt < 4; mt++)
#pragma unroll
        for (int kc = 0; kc < 8; kc++) {
            int r = rbase + mt * 16 + (l >> 2);
            int k = kc * 16 + (l & 3) * 2;
            float2 v0 = *(const float2*)(whh + (size_t)r * 128 + k);
            float2 v1 = *(const float2*)(whh + (size_t)(r + 8) * 128 + k);
            float2 v2 = *(const float2*)(whh + (size_t)r * 128 + k + 8);
            float2 v3 = *(const float2*)(whh + (size_t)(r + 8) * 128 + k + 8);
            A[mt][kc][0] = h2u(__float22half2_rn(v0));
            A[mt][kc][1] = h2u(__float22half2_rn(v1));
            A[mt][kc][2] = h2u(__float22half2_rn(v2));
            A[mt][kc][3] = h2u(__float22half2_rn(v3));
        }

    // zero hN (rows 2-7 remain zero forever): 8*136 = 1088 halves = 544 half2
    for (int i = tid; i < 544; i += 256) ((__half2*)&hN[0][0])[i] = __float2half2_rn(0.f);

    // pointwise ownership: all 256 threads, item (u = tid>>1, p = tid&1)
    int u = tid >> 1, p = tid & 1;
    int pathg = pg * 2 + p;
    long stride = dir ? -1024 : 1024;
    const __half* gp = g_gxh + (size_t)pathg * Tn * 1024 + dir * 512 + u
                     + (dir ? (size_t)(Tn - 1) * 1024 : 0);
    float gi = __half2float(gp[0]),   gf = __half2float(gp[128]);
    float gg = __half2float(gp[256]), go = __half2float(gp[384]);

    float c = 0.f, hval = 0.f;
    unsigned sb = (unsigned)__cvta_generic_to_shared(&hN[0][0]);
    unsigned ldaddr_base = sb + ((l & 7) * 136 + (l >> 3) * 8) * 2;

    __syncthreads();

    for (int s = 0; s < Tn; s++) {
        // prefetch next step's gx (overlaps MMA phase)
        const __half* gn = gp + ((s + 1 < Tn) ? stride : 0);
        float ni = __half2float(gn[0]),   nf = __half2float(gn[128]);
        float ng = __half2float(gn[256]), no_ = __half2float(gn[384]);

        unsigned b[8][2];
#pragma unroll
        for (int ks = 0; ks < 4; ks++) {
            unsigned r0, r1, r2, r3;
            ldm_x4(r0, r1, r2, r3, ldaddr_base + ks * 64);
            b[2 * ks][0] = r0;     b[2 * ks][1] = r1;
            b[2 * ks + 1][0] = r2; b[2 * ks + 1][1] = r3;
        }
        // 4 independent depth-8 chains (one per m-tile)
        float C[4][4];
#pragma unroll
        for (int mt = 0; mt < 4; mt++) {
            C[mt][0] = 0.f; C[mt][1] = 0.f; C[mt][2] = 0.f; C[mt][3] = 0.f;
        }
#pragma unroll
        for (int kc = 0; kc < 8; kc++) {
#pragma unroll
            for (int mt = 0; mt < 4; mt++)
                mma16816(C[mt], A[mt][kc], b[kc][0], b[kc][1]);
        }

        {
            int rr = rbase + (l >> 2), cc = (l & 3) * 2;
#pragma unroll
            for (int mt = 0; mt < 4; mt++) {
                *(float2*)&pre[rr + mt * 16][cc]     = make_float2(C[mt][0], C[mt][1]);
                *(float2*)&pre[rr + mt * 16 + 8][cc] = make_float2(C[mt][2], C[mt][3]);
            }
        }
        __syncthreads();

        float iv = siga (gi + pre[u][p]);
        float fv = siga (gf + pre[128 + u][p]);
        float gv = tanha(gg + pre[256 + u][p]);
        float ov = siga (go + pre[384 + u][p]);
        c = fv * c + iv * gv;
        hval = ov * tanha(c);
        hN[p][u] = __float2half(hval);

        gi = ni; gf = nf; gg = ng; go = no_;
        gp = gn;
        __syncthreads();
    }
    g_ctx[pathg * 256 + dir * 128 + u] = hval;
}

// ---------------- attention --------------------------------------------------
__global__ void __launch_bounds__(256) att1_kernel(const float* __restrict__ d1b,
                                                   const float* __restrict__ d2w,
                                                   const float* __restrict__ d2b) {
    __shared__ float cat[512];
    __shared__ float red[256];
    int p = blockIdx.x, tid = threadIdx.x;
    cat[tid]       = g_ctx[p * 256 + tid];
    cat[256 + tid] = g_u[tid];
    __syncthreads();
    float acc = d1b[tid];
#pragma unroll 8
    for (int k = 0; k < 512; k++) acc += cat[k] * g_d1wT[k * 256 + tid];
    red[tid] = tanh_(acc) * d2w[tid];
    __syncthreads();
    for (int s = 128; s > 0; s >>= 1) {
        if (tid < s) red[tid] += red[tid + s];
        __syncthreads();
    }
    if (tid == 0) g_score[p] = red[0] + d2b[0];
}

__global__ void __launch_bounds__(256) att2_kernel(const float* __restrict__ d1b) {
    __shared__ float al[128];
    __shared__ float red[128];
    __shared__ float cat[512];
    int tid = threadIdx.x;
    cat[tid] = g_u[tid];
    if (tid < 128) red[tid] = g_score[tid];
    __syncthreads();
    for (int s = 64; s > 0; s >>= 1) {
        if (tid < s) red[tid] = fmaxf(red[tid], red[tid + s]);
        __syncthreads();
    }
    float m = red[0];
    __syncthreads();
    if (tid < 128) { float e = __expf(g_score[tid] - m); al[tid] = e; red[tid] = e; }
    __syncthreads();
    for (int s = 64; s > 0; s >>= 1) {
        if (tid < s) red[tid] += red[tid + s];
        __syncthreads();
    }
    float inv = __fdividef(1.f, red[0]);
    float o = 0.f;
#pragma unroll 8
    for (int p = 0; p < 128; p++) o += al[p] * g_ctx[p * 256 + tid];
    cat[256 + tid] = o * inv;
    __syncthreads();
    float acc = d1b[tid];
#pragma unroll 8
    for (int k = 0; k < 512; k++) acc += cat[k] * g_d1wT[k * 256 + tid];
    __syncthreads();
    g_u[tid] = acc;
}

__global__ void __launch_bounds__(256) final_kernel(const float* __restrict__ d2w,
                                                    const float* __restrict__ d2b,
                                                    float* __restrict__ out) {
    __shared__ float red[256];
    int tid = threadIdx.x;
    red[tid] = fmaxf(g_u[tid], 0.f) * d2w[tid];
    __syncthreads();
    for (int s = 128; s > 0; s >>= 1) {
        if (tid < s) red[tid] += red[tid + s];
        __syncthreads();
    }
    if (tid == 0) out[0] = __fdividef(1.f, 1.f + __expf(-(red[0] + d2b[0])));
}

// ---------------- launch ------------------------------------------------------
extern "C" void kernel_launch(void* const* d_in, const int* in_sizes, int n_in,
                              void* d_out, int out_size) {
    const int*   path   = (const int*)  d_in[0];
    const int*   query  = (const int*)  d_in[1];
    const float* embA   = (const float*)d_in[2];
    const float* embB   = (const float*)d_in[3];
    const float* conv_w = (const float*)d_in[4];
    const float* conv_b = (const float*)d_in[5];
    const float* wihf   = (const float*)d_in[6];
    const float* whhf   = (const float*)d_in[7];
    const float* bihf   = (const float*)d_in[8];
    const float* bhhf   = (const float*)d_in[9];
    const float* wihb   = (const float*)d_in[10];
    const float* whhb   = (const float*)d_in[11];
    const float* bihb   = (const float*)d_in[12];
    const float* bhhb   = (const float*)d_in[13];
    const float* d1w    = (const float*)d_in[14];
    const float* d1b    = (const float*)d_in[15];
    const float* d2w    = (const float*)d_in[16];
    const float* d2b    = (const float*)d_in[17];
    float* out = (float*)d_out;

    const int mma_smem = 2 * 128 * SROW * 2;           // 69632 B
    cudaFuncSetAttribute(gemm_kernel, cudaFuncAttributeMaxDynamicSharedMemorySize, mma_smem);
    cudaFuncSetAttribute(convgemm_kernel, cudaFuncAttributeMaxDynamicSharedMemorySize, mma_smem);

    setup_kernel<<<PREP_BLKS + 32768 + 1, 256>>>(path, query, embA, embB, conv_w, d1w,
                                                 wihf, wihb, bihf, bhhf, bihb, bhhb);
    convgemm_kernel<<<510, 256, mma_smem>>>(conv_b);
    gemm_kernel<<<dim3(509, 8), 256, mma_smem>>>();
    lstm_kernel<<<128, 256>>>(whhf, whhb);
    for (int it = 0; it < 2; it++) {
        att1_kernel<<<128, 256>>>(d1b, d2w, d2b);
        att2_kernel<<<1, 256>>>(d1b);
    }
    final_kernel<<<1, 256>>>(d2w, d2b, out);
}

// round 11
// speedup vs baseline: 1.2811x; 1.0360x over previous
#include <cuda_runtime.h>
#include <cuda_fp16.h>
#include <math.h>

#define Pn 128
#define Ln 512
#define En 256
#define Fn 128
#define Tn 509
#define SROW 136   // halves per smem row (272 B: ldmatrix conflict-free)

// ---------------- scratch (device globals; allocation is forbidden) ----------
__device__ __half  g_emb[(size_t)Pn * Ln * En];    // fp16 embedded tokens [p][l][e]
__device__ __half  g_conv[(size_t)Pn * 510 * Fn];  // conv+relu output [p][t'][f]
__device__ __half  g_gxh[(size_t)Pn * Tn * 1024];  // input gates fp16 [p*T][fwd512|bwd512]
__device__ float   g_ctx[Pn * En];                 // BiLSTM context [p][2H]
__device__ __half  g_cwh[Fn * 768];                // conv weights [f][w*256+e] fp16
__device__ float   g_d1wT[512 * 256];              // d1_w transposed [k][e]
__device__ __half  g_wh [1024 * 128];              // W_ih fp16 [n(fwd512|bwd512)][k]
__device__ float   g_bias[1024];                   // combined b_ih + b_hh
__device__ float   g_score[Pn];
__device__ float   g_u[En];

// ---------------- helpers ----------------------------------------------------
__device__ __forceinline__ float sigf(float x) {
    return __fdividef(1.f, 1.f + __expf(-x));
}
__device__ __forceinline__ float tanh_(float x) {
    return __fdividef(2.f, 1.f + __expf(-2.f * x)) - 1.f;
}
// HW tanh (sm_75+), ~5e-4 abs err — used only inside the LSTM recurrence
__device__ __forceinline__ float tanha(float x) {
    float y;
    asm("tanh.approx.f32 %0, %1;" : "=f"(y) : "f"(x));
    return y;
}
__device__ __forceinline__ float siga(float x) {
    return fmaf(0.5f, tanha(0.5f * x), 0.5f);
}
union UH2 { unsigned int u; __half2 h; };
__device__ __forceinline__ unsigned h2u(__half2 h) { UH2 v; v.h = h; return v.u; }
__device__ __forceinline__ __half2 u2h(unsigned x) { UH2 v; v.u = x; return v.h; }

__device__ __forceinline__ void ldm_x4(unsigned& r0, unsigned& r1, unsigned& r2, unsigned& r3,
                                       unsigned addr) {
    asm volatile("ldmatrix.sync.aligned.m8n8.x4.shared.b16 {%0,%1,%2,%3}, [%4];"
                 : "=r"(r0), "=r"(r1), "=r"(r2), "=r"(r3) : "r"(addr));
}
__device__ __forceinline__ void mma16816(float* c, const unsigned* a, unsigned b0, unsigned b1) {
    asm volatile("mma.sync.aligned.m16n8k16.row.col.f32.f16.f16.f32 "
                 "{%0,%1,%2,%3}, {%4,%5,%6,%7}, {%8,%9}, {%0,%1,%2,%3};"
                 : "+f"(c[0]), "+f"(c[1]), "+f"(c[2]), "+f"(c[3])
                 : "r"(a[0]), "r"(a[1]), "r"(a[2]), "r"(a[3]), "r"(b0), "r"(b1));
}

// ---------------- launch 1: setup (prep + init_u + embed fused) ---------------
#define PREP_BLKS 1412
__global__ void __launch_bounds__(256) setup_kernel(
        const int* __restrict__ path, const int* __restrict__ query,
        const float* __restrict__ embA, const float* __restrict__ embB,
        const float* __restrict__ conv_w, const float* __restrict__ d1w,
        const float* __restrict__ wihf, const float* __restrict__ wihb,
        const float* __restrict__ bihf, const float* __restrict__ bhhf,
        const float* __restrict__ bihb, const float* __restrict__ bhhb) {
    int bx = blockIdx.x;
    if (bx < PREP_BLKS) {
        int idx = bx * 256 + threadIdx.x;
        if (idx < 98304) {                        // cwh[f][w*256+e] = conv_w[f][e][w]
            int f = idx / 768, r = idx - f * 768;
            int w = r >> 8, e = r & 255;
            g_cwh[idx] = __float2half(conv_w[(size_t)f * 768 + e * 3 + w]);
        } else if (idx < 98304 + 131072) {        // d1wT[k*256+e]
            int j = idx - 98304;
            int e = j & 255, k = j >> 8;
            g_d1wT[j] = d1w[(size_t)e * 512 + k];
        } else if (idx < 229376 + 131072) {       // g_wh[n][k] fp16
            int j = idx - 229376;
            int k = j & 127, n = j >> 7;
            float w = (n < 512) ? wihf[(size_t)n * 128 + k] : wihb[(size_t)(n - 512) * 128 + k];
            g_wh[j] = __float2half(w);
        } else if (idx < 360448 + 1024) {         // g_bias[n]
            int n = idx - 360448;
            g_bias[n] = (n < 512) ? (bihf[n] + bhhf[n]) : (bihb[n - 512] + bhhb[n - 512]);
        }
    } else if (bx < PREP_BLKS + 32768) {          // embedding gather
        int b = bx - PREP_BLKS;
        int p = b >> 8;
        int l = (b & 255) * 2 + (threadIdx.x >> 7);
        int t = threadIdx.x & 127;
        int tok = path[p * Ln + l];
        float2 v = *(const float2*)(embA + (size_t)tok * En + 2 * t);
        *(__half2*)(g_emb + ((size_t)p * Ln + l) * En + 2 * t) = __float22half2_rn(v);
    } else {                                      // init u
        g_u[threadIdx.x] = embB[(size_t)query[0] * En + threadIdx.x];
    }
}

// ---------------- launch 2: conv as GEMM (tensor cores) -----------------------
__global__ void __launch_bounds__(256) convgemm_kernel(const float* __restrict__ conv_b) {
    extern __shared__ __half smh[];
    __half* As = smh;                 // [128 m][SROW]
    __half* Bs = smh + 128 * SROW;    // [128 f][SROW]
    __shared__ float bias_s[128];

    int row0 = blockIdx.x * 128;
    int tid  = threadIdx.x;
    int wid  = tid >> 5, lane = tid & 31;
    int m0 = (wid >> 2) * 64;
    int n0 = (wid & 3) * 32;

    if (tid < 128) bias_s[tid] = conv_b[tid];

    unsigned sbase = (unsigned)__cvta_generic_to_shared(smh);
    unsigned aAddr[4], bAddr[2];
#pragma unroll
    for (int mi = 0; mi < 4; mi++) {
        int r = m0 + mi * 16 + (lane & 15);
        int ch = (lane >> 4) * 8;
        aAddr[mi] = sbase + (r * SROW + ch) * 2;
    }
#pragma unroll
    for (int bj = 0; bj < 2; bj++) {
        int r = n0 + bj * 16 + (lane & 7) + ((lane >> 4) << 3);
        int ch = ((lane >> 3) & 1) * 8;
        bAddr[bj] = sbase + (128 * SROW + r * SROW + ch) * 2;
    }

    float acc[4][4][4];
#pragma unroll
    for (int mi = 0; mi < 4; mi++)
#pragma unroll
        for (int nj = 0; nj < 4; nj++)
#pragma unroll
            for (int q = 0; q < 4; q++) acc[mi][nj][q] = 0.f;

    for (int kt = 0; kt < 6; kt++) {
        int k0 = kt * 128;
        if (kt) __syncthreads();
        for (int idx = tid; idx < 2048; idx += 256) {
            int rr = idx >> 4, c = idx & 15;
            int gr = row0 + rr;
            int p = gr / 510, t = gr - p * 510;
            const uint4* asrc = (const uint4*)(g_emb + ((size_t)p * Ln + t) * En + k0);
            *(uint4*)(As + rr * SROW + c * 8) = asrc[c];
            const uint4* bsrc = (const uint4*)(g_cwh + (size_t)rr * 768 + k0);
            *(uint4*)(Bs + rr * SROW + c * 8) = bsrc[c];
        }
        __syncthreads();

#pragma unroll
        for (int ks = 0; ks < 8; ks++) {
            unsigned a[4][4], b[2][4];
#pragma unroll
            for (int mi = 0; mi < 4; mi++)
                ldm_x4(a[mi][0], a[mi][1], a[mi][2], a[mi][3], aAddr[mi] + ks * 32);
#pragma unroll
            for (int bj = 0; bj < 2; bj++)
                ldm_x4(b[bj][0], b[bj][1], b[bj][2], b[bj][3], bAddr[bj] + ks * 32);
#pragma unroll
            for (int mi = 0; mi < 4; mi++)
#pragma unroll
                for (int nj = 0; nj < 4; nj++)
                    mma16816(acc[mi][nj], a[mi], b[nj >> 1][(nj & 1) * 2], b[nj >> 1][(nj & 1) * 2 + 1]);
        }
    }

    int qr = lane >> 2, qc = (lane & 3) * 2;
#pragma unroll
    for (int mi = 0; mi < 4; mi++) {
#pragma unroll
        for (int nj = 0; nj < 4; nj++) {
            int cc = n0 + nj * 8 + qc;
            float bx = bias_s[cc], by = bias_s[cc + 1];
            int r1 = row0 + m0 + mi * 16 + qr;
            __half2 v0 = __floats2half2_rn(fmaxf(acc[mi][nj][0] + bx, 0.f),
                                           fmaxf(acc[mi][nj][1] + by, 0.f));
            *(__half2*)(g_conv + (size_t)r1 * 128 + cc) = v0;
            __half2 v1 = __floats2half2_rn(fmaxf(acc[mi][nj][2] + bx, 0.f),
                                           fmaxf(acc[mi][nj][3] + by, 0.f));
            *(__half2*)(g_conv + (size_t)(r1 + 8) * 128 + cc) = v1;
        }
    }
}

// ---------------- launch 3: input-gate GEMM (pool fused into A-load) ----------
__global__ void __launch_bounds__(256) gemm_kernel() {
    extern __shared__ __half smh[];
    __half* As = smh;                 // [128 m][SROW]
    __half* Bs = smh + 128 * SROW;    // [128 n][SROW]
    __shared__ float bias_s[128];

    int row0 = blockIdx.x * 128;
    int col0 = blockIdx.y * 128;
    int tid  = threadIdx.x;
    int wid  = tid >> 5, lane = tid & 31;
    int m0 = (wid >> 2) * 64;
    int n0 = (wid & 3) * 32;

    if (tid < 128) bias_s[tid] = g_bias[col0 + tid];

    {
        const uint4* bsrc = (const uint4*)(g_wh + (size_t)col0 * 128);
        for (int idx = tid; idx < 2048; idx += 256) {
            int r = idx >> 4, c = idx & 15;
            int gr = row0 + r;
            int p = gr / Tn, t = gr - p * Tn;
            const uint4* csrc = (const uint4*)(g_conv + ((size_t)p * 510 + t) * 128);
            uint4 x = csrc[c], y = csrc[c + 16];
            UH2 ax, ay, r0, r1, r2, r3;
            ax.u = x.x; ay.u = y.x; r0.h = __hmax2(ax.h, ay.h);
            ax.u = x.y; ay.u = y.y; r1.h = __hmax2(ax.h, ay.h);
            ax.u = x.z; ay.u = y.z; r2.h = __hmax2(ax.h, ay.h);
            ax.u = x.w; ay.u = y.w; r3.h = __hmax2(ax.h, ay.h);
            uint4 m4 = make_uint4(r0.u, r1.u, r2.u, r3.u);
            *(uint4*)(As + r * SROW + c * 8) = m4;
            *(uint4*)(Bs + r * SROW + c * 8) = bsrc[r * 16 + c];
        }
    }
    __syncthreads();

    unsigned sbase = (unsigned)__cvta_generic_to_shared(smh);
    unsigned aAddr[4], bAddr[2];
#pragma unroll
    for (int mi = 0; mi < 4; mi++) {
        int r = m0 + mi * 16 + (lane & 15);
        int ch = (lane >> 4) * 8;
        aAddr[mi] = sbase + (r * SROW + ch) * 2;
    }
#pragma unroll
    for (int bj = 0; bj < 2; bj++) {
        int r = n0 + bj * 16 + (lane & 7) + ((lane >> 4) << 3);
        int ch = ((lane >> 3) & 1) * 8;
        bAddr[bj] = sbase + (128 * SROW + r * SROW + ch) * 2;
    }

    float acc[4][4][4];
#pragma unroll
    for (int mi = 0; mi < 4; mi++)
#pragma unroll
        for (int nj = 0; nj < 4; nj++)
#pragma unroll
            for (int q = 0; q < 4; q++) acc[mi][nj][q] = 0.f;

#pragma unroll
    for (int ks = 0; ks < 8; ks++) {
        unsigned a[4][4], b[2][4];
#pragma unroll
        for (int mi = 0; mi < 4; mi++)
            ldm_x4(a[mi][0], a[mi][1], a[mi][2], a[mi][3], aAddr[mi] + ks * 32);
#pragma unroll
        for (int bj = 0; bj < 2; bj++)
            ldm_x4(b[bj][0], b[bj][1], b[bj][2], b[bj][3], bAddr[bj] + ks * 32);
#pragma unroll
        for (int mi = 0; mi < 4; mi++)
#pragma unroll
            for (int nj = 0; nj < 4; nj++)
                mma16816(acc[mi][nj], a[mi], b[nj >> 1][(nj & 1) * 2], b[nj >> 1][(nj & 1) * 2 + 1]);
    }

    int qr = lane >> 2, qc = (lane & 3) * 2;
#pragma unroll
    for (int mi = 0; mi < 4; mi++) {
#pragma unroll
        for (int nj = 0; nj < 4; nj++) {
            int cc = n0 + nj * 8 + qc;
            float bx = bias_s[cc], by = bias_s[cc + 1];
            size_t base = (size_t)(row0 + m0 + mi * 16 + qr) * 1024 + col0 + cc;
            *(__half2*)(g_gxh + base) = __floats2half2_rn(acc[mi][nj][0] + bx, acc[mi][nj][1] + by);
            *(__half2*)(g_gxh + base + 8 * 1024) = __floats2half2_rn(acc[mi][nj][2] + bx, acc[mi][nj][3] + by);
        }
    }
}

// ---------------- launch 4: LSTM recurrence v5 (warp-local gates) -------------
// 128 CTAs: bid=(pg<<1)|dir, paths pg*2, pg*2+1; 256 threads (8 warps).
// Gate-interleaved A rows: warp w's 4 m-tiles = gates i,f,g,o of units
// [w*16, w*16+16). All preacts a warp needs are produced BY that warp ->
// redistribution is warp-private (512B smem patch + __syncwarp), and only
// ONE __syncthreads per step (hN publish; hN double-buffered).
__global__ void __launch_bounds__(256, 1) lstm_kernel(const float* __restrict__ whhf,
                                                      const float* __restrict__ whhb) {
    __shared__ float preW[8][4][16][2];              // per-warp patches, 4 KB
    __shared__ __align__(16) __half hN[2][8][136];   // [buf][path-slot][unit]

    int bid = blockIdx.x;
    int dir = bid & 1;
    int pg  = bid >> 1;
    int tid = threadIdx.x;
    int w   = tid >> 5, l = tid & 31;

    const float* whh = dir ? whhb : whhf;

    // A fragments: tile mt = gate mt of units [w*16, w*16+16)
    unsigned A[4][8][4];
#pragma unroll
    for (int mt = 0; mt < 4; mt++)
#pragma unroll
        for (int kc = 0; kc < 8; kc++) {
            int r = mt * 128 + w * 16 + (l >> 2);
            int k = kc * 16 + (l & 3) * 2;
            float2 v0 = *(const float2*)(whh + (size_t)r * 128 + k);
            float2 v1 = *(const float2*)(whh + (size_t)(r + 8) * 128 + k);
            float2 v2 = *(const float2*)(whh + (size_t)r * 128 + k + 8);
            float2 v3 = *(const float2*)(whh + (size_t)(r + 8) * 128 + k + 8);
            A[mt][kc][0] = h2u(__float22half2_rn(v0));
            A[mt][kc][1] = h2u(__float22half2_rn(v1));
            A[mt][kc][2] = h2u(__float22half2_rn(v2));
            A[mt][kc][3] = h2u(__float22half2_rn(v3));
        }

    // zero both hN buffers: 2*8*136 = 2176 halves = 1088 half2
    for (int i = tid; i < 1088; i += 256) ((__half2*)&hN[0][0][0])[i] = __float2half2_rn(0.f);

    // pointwise ownership: item (unit = w*16 + (l>>1), path = l&1)
    int ul = l >> 1, p = l & 1;
    int u  = w * 16 + ul;
    int pathg = pg * 2 + p;
    long stride = dir ? -1024 : 1024;
    const __half* gp = g_gxh + (size_t)pathg * Tn * 1024 + dir * 512 + u
                     + (dir ? (size_t)(Tn - 1) * 1024 : 0);
    float gi = __half2float(gp[0]),   gf = __half2float(gp[128]);
    float gg = __half2float(gp[256]), go = __half2float(gp[384]);

    float c = 0.f, hval = 0.f;
    unsigned sb = (unsigned)__cvta_generic_to_shared(&hN[0][0][0]);
    unsigned ldlane = ((l & 7) * 136 + (l >> 3) * 8) * 2;
    int strow = l >> 2;        // store row for lanes with (l&3)==0

    __syncthreads();

    for (int s = 0; s < Tn; s++) {
        int cb = s & 1;
        // prefetch next step's gx (overlaps MMA phase)
        const __half* gn = gp + ((s + 1 < Tn) ? stride : 0);
        float ni = __half2float(gn[0]),   nf = __half2float(gn[128]);
        float ng = __half2float(gn[256]), no_ = __half2float(gn[384]);

        unsigned b[8][2];
        unsigned ldbase = sb + cb * (8 * 136 * 2) + ldlane;
#pragma unroll
        for (int ks = 0; ks < 4; ks++) {
            unsigned r0, r1, r2, r3;
            ldm_x4(r0, r1, r2, r3, ldbase + ks * 64);
            b[2 * ks][0] = r0;     b[2 * ks][1] = r1;
            b[2 * ks + 1][0] = r2; b[2 * ks + 1][1] = r3;
        }
        // 4 independent depth-8 chains (one per gate tile)
        float C[4][4];
#pragma unroll
        for (int mt = 0; mt < 4; mt++) {
            C[mt][0] = 0.f; C[mt][1] = 0.f; C[mt][2] = 0.f; C[mt][3] = 0.f;
        }
#pragma unroll
        for (int kc = 0; kc < 8; kc++) {
#pragma unroll
            for (int mt = 0; mt < 4; mt++)
                mma16816(C[mt], A[mt][kc], b[kc][0], b[kc][1]);
        }

        // warp-private exchange: lanes holding cols 0-1 store; everyone reads
        if ((l & 3) == 0) {
#pragma unroll
            for (int mt = 0; mt < 4; mt++) {
                *(float2*)&preW[w][mt][strow][0]     = make_float2(C[mt][0], C[mt][1]);
                *(float2*)&preW[w][mt][strow + 8][0] = make_float2(C[mt][2], C[mt][3]);
            }
        }
        __syncwarp();

        float iv = siga (gi + preW[w][0][ul][p]);
        float fv = siga (gf + preW[w][1][ul][p]);
        float gv = tanha(gg + preW[w][2][ul][p]);
        float ov = siga (go + preW[w][3][ul][p]);
        c = fv * c + iv * gv;
        hval = ov * tanha(c);
        hN[cb ^ 1][p][u] = __float2half(hval);

        gi = ni; gf = nf; gg = ng; go = no_;
        gp = gn;
        __syncthreads();
    }
    g_ctx[pathg * 256 + dir * 128 + u] = hval;
}

// ---------------- attention --------------------------------------------------
__global__ void __launch_bounds__(256) att1_kernel(const float* __restrict__ d1b,
                                                   const float* __restrict__ d2w,
                                                   const float* __restrict__ d2b) {
    __shared__ float cat[512];
    __shared__ float red[256];
    int p = blockIdx.x, tid = threadIdx.x;
    cat[tid]       = g_ctx[p * 256 + tid];
    cat[256 + tid] = g_u[tid];
    __syncthreads();
    float acc = d1b[tid];
#pragma unroll 8
    for (int k = 0; k < 512; k++) acc += cat[k] * g_d1wT[k * 256 + tid];
    red[tid] = tanh_(acc) * d2w[tid];
    __syncthreads();
    for (int s = 128; s > 0; s >>= 1) {
        if (tid < s) red[tid] += red[tid + s];
        __syncthreads();
    }
    if (tid == 0) g_score[p] = red[0] + d2b[0];
}

__global__ void __launch_bounds__(256) att2_kernel(const float* __restrict__ d1b) {
    __shared__ float al[128];
    __shared__ float red[128];
    __shared__ float cat[512];
    int tid = threadIdx.x;
    cat[tid] = g_u[tid];
    if (tid < 128) red[tid] = g_score[tid];
    __syncthreads();
    for (int s = 64; s > 0; s >>= 1) {
        if (tid < s) red[tid] = fmaxf(red[tid], red[tid + s]);
        __syncthreads();
    }
    float m = red[0];
    __syncthreads();
    if (tid < 128) { float e = __expf(g_score[tid] - m); al[tid] = e; red[tid] = e; }
    __syncthreads();
    for (int s = 64; s > 0; s >>= 1) {
        if (tid < s) red[tid] += red[tid + s];
        __syncthreads();
    }
    float inv = __fdividef(1.f, red[0]);
    float o = 0.f;
#pragma unroll 8
    for (int p = 0; p < 128; p++) o += al[p] * g_ctx[p * 256 + tid];
    cat[256 + tid] = o * inv;
    __syncthreads();
    float acc = d1b[tid];
#pragma unroll 8
    for (int k = 0; k < 512; k++) acc += cat[k] * g_d1wT[k * 256 + tid];
    __syncthreads();
    g_u[tid] = acc;
}

__global__ void __launch_bounds__(256) final_kernel(const float* __restrict__ d2w,
                                                    const float* __restrict__ d2b,
                                                    float* __restrict__ out) {
    __shared__ float red[256];
    int tid = threadIdx.x;
    red[tid] = fmaxf(g_u[tid], 0.f) * d2w[tid];
    __syncthreads();
    for (int s = 128; s > 0; s >>= 1) {
        if (tid < s) red[tid] += red[tid + s];
        __syncthreads();
    }
    if (tid == 0) out[0] = __fdividef(1.f, 1.f + __expf(-(red[0] + d2b[0])));
}

// ---------------- launch ------------------------------------------------------
extern "C" void kernel_launch(void* const* d_in, const int* in_sizes, int n_in,
                              void* d_out, int out_size) {
    const int*   path   = (const int*)  d_in[0];
    const int*   query  = (const int*)  d_in[1];
    const float* embA   = (const float*)d_in[2];
    const float* embB   = (const float*)d_in[3];
    const float* conv_w = (const float*)d_in[4];
    const float* conv_b = (const float*)d_in[5];
    const float* wihf   = (const float*)d_in[6];
    const float* whhf   = (const float*)d_in[7];
    const float* bihf   = (const float*)d_in[8];
    const float* bhhf   = (const float*)d_in[9];
    const float* wihb   = (const float*)d_in[10];
    const float* whhb   = (const float*)d_in[11];
    const float* bihb   = (const float*)d_in[12];
    const float* bhhb   = (const float*)d_in[13];
    const float* d1w    = (const float*)d_in[14];
    const float* d1b    = (const float*)d_in[15];
    const float* d2w    = (const float*)d_in[16];
    const float* d2b    = (const float*)d_in[17];
    float* out = (float*)d_out;

    const int mma_smem = 2 * 128 * SROW * 2;           // 69632 B
    cudaFuncSetAttribute(gemm_kernel, cudaFuncAttributeMaxDynamicSharedMemorySize, mma_smem);
    cudaFuncSetAttribute(convgemm_kernel, cudaFuncAttributeMaxDynamicSharedMemorySize, mma_smem);

    setup_kernel<<<PREP_BLKS + 32768 + 1, 256>>>(path, query, embA, embB, conv_w, d1w,
                                                 wihf, wihb, bihf, bhhf, bihb, bhhb);
    convgemm_kernel<<<510, 256, mma_smem>>>(conv_b);
    gemm_kernel<<<dim3(509, 8), 256, mma_smem>>>();
    lstm_kernel<<<128, 256>>>(whhf, whhb);
    for (int it = 0; it < 2; it++) {
        att1_kernel<<<128, 256>>>(d1b, d2w, d2b);
        att2_kernel<<<1, 256>>>(d1b);
    }
    final_kernel<<<1, 256>>>(d2w, d2b, out);
}

// round 12
// speedup vs baseline: 1.2928x; 1.0091x over previous
#include <cuda_runtime.h>
#include <cuda_fp16.h>
#include <math.h>

#define Pn 128
#define Ln 512
#define En 256
#define Fn 128
#define Tn 509
#define SROW 136   // padded halves per smem row (272 B: ldmatrix conflict-free)

// ---------------- scratch (device globals; allocation is forbidden) ----------
__device__ __half  g_conv[(size_t)Pn * 510 * Fn];  // conv+relu output [p][t'][f]
__device__ __half  g_gxh[(size_t)Pn * Tn * 1024];  // input gates fp16 [p*T][fwd512|bwd512]
__device__ float   g_ctx[Pn * En];                 // BiLSTM context [p][2H]
__device__ __half  g_cwh[Fn * 768];                // conv weights [f][w*256+e] fp16
__device__ float   g_d1wT[512 * 256];              // d1_w transposed [k][e]
__device__ __half  g_wh [1024 * 128];              // W_ih fp16 [n(fwd512|bwd512)][k]
__device__ float   g_bias[1024];                   // combined b_ih + b_hh
__device__ float   g_score[Pn];
__device__ float   g_u[En];

// ---------------- helpers ----------------------------------------------------
__device__ __forceinline__ float sigf(float x) {
    return __fdividef(1.f, 1.f + __expf(-x));
}
__device__ __forceinline__ float tanh_(float x) {
    return __fdividef(2.f, 1.f + __expf(-2.f * x)) - 1.f;
}
// HW tanh (sm_75+), ~5e-4 abs err — used only inside the LSTM recurrence
__device__ __forceinline__ float tanha(float x) {
    float y;
    asm("tanh.approx.f32 %0, %1;" : "=f"(y) : "f"(x));
    return y;
}
__device__ __forceinline__ float siga(float x) {
    return fmaf(0.5f, tanha(0.5f * x), 0.5f);
}
union UH2 { unsigned int u; __half2 h; };
__device__ __forceinline__ unsigned h2u(__half2 h) { UH2 v; v.h = h; return v.u; }
__device__ __forceinline__ __half2 u2h(unsigned x) { UH2 v; v.u = x; return v.h; }

__device__ __forceinline__ void ldm_x4(unsigned& r0, unsigned& r1, unsigned& r2, unsigned& r3,
                                       unsigned addr) {
    asm volatile("ldmatrix.sync.aligned.m8n8.x4.shared.b16 {%0,%1,%2,%3}, [%4];"
                 : "=r"(r0), "=r"(r1), "=r"(r2), "=r"(r3) : "r"(addr));
}
__device__ __forceinline__ void mma16816(float* c, const unsigned* a, unsigned b0, unsigned b1) {
    asm volatile("mma.sync.aligned.m16n8k16.row.col.f32.f16.f16.f32 "
                 "{%0,%1,%2,%3}, {%4,%5,%6,%7}, {%8,%9}, {%0,%1,%2,%3};"
                 : "+f"(c[0]), "+f"(c[1]), "+f"(c[2]), "+f"(c[3])
                 : "r"(a[0]), "r"(a[1]), "r"(a[2]), "r"(a[3]), "r"(b0), "r"(b1));
}

// ---------------- launch 1: setup (weight prep + init_u) ----------------------
#define PREP_BLKS 1412
__global__ void __launch_bounds__(256) setup_kernel(
        const int* __restrict__ query,
        const float* __restrict__ embB,
        const float* __restrict__ conv_w, const float* __restrict__ d1w,
        const float* __restrict__ wihf, const float* __restrict__ wihb,
        const float* __restrict__ bihf, const float* __restrict__ bhhf,
        const float* __restrict__ bihb, const float* __restrict__ bhhb) {
    int bx = blockIdx.x;
    if (bx < PREP_BLKS) {
        int idx = bx * 256 + threadIdx.x;
        if (idx < 98304) {                        // cwh[f][w*256+e] = conv_w[f][e][w]
            int f = idx / 768, r = idx - f * 768;
            int w = r >> 8, e = r & 255;
            g_cwh[idx] = __float2half(conv_w[(size_t)f * 768 + e * 3 + w]);
        } else if (idx < 98304 + 131072) {        // d1wT[k*256+e]
            int j = idx - 98304;
            int e = j & 255, k = j >> 8;
            g_d1wT[j] = d1w[(size_t)e * 512 + k];
        } else if (idx < 229376 + 131072) {       // g_wh[n][k] fp16
            int j = idx - 229376;
            int k = j & 127, n = j >> 7;
            float w = (n < 512) ? wihf[(size_t)n * 128 + k] : wihb[(size_t)(n - 512) * 128 + k];
            g_wh[j] = __float2half(w);
        } else if (idx < 360448 + 1024) {         // g_bias[n]
            int n = idx - 360448;
            g_bias[n] = (n < 512) ? (bihf[n] + bhhf[n]) : (bihb[n - 512] + bhhb[n - 512]);
        }
    } else {                                      // init u
        g_u[threadIdx.x] = embB[(size_t)query[0] * En + threadIdx.x];
    }
}

// ---------------- launch 2: conv as GEMM with fused embedding gather ----------
// A row for (p,t) = fp16(embA[path[p][t..t+2]][:]) gathered inline per k-chunk.
// Chunk of 8 floats never crosses a token boundary (offsets 128-aligned in 256).
__global__ void __launch_bounds__(256) convgemm_kernel(const int* __restrict__ path,
                                                       const float* __restrict__ embA,
                                                       const float* __restrict__ conv_b) {
    extern __shared__ __half smh[];
    __half* As = smh;                 // [128 m][SROW]
    __half* Bs = smh + 128 * SROW;    // [128 f][SROW]
    __shared__ float bias_s[128];

    int row0 = blockIdx.x * 128;
    int tid  = threadIdx.x;
    int wid  = tid >> 5, lane = tid & 31;
    int m0 = (wid >> 2) * 64;
    int n0 = (wid & 3) * 32;

    if (tid < 128) bias_s[tid] = conv_b[tid];

    unsigned sbase = (unsigned)__cvta_generic_to_shared(smh);
    unsigned aAddr[4], bAddr[2];
#pragma unroll
    for (int mi = 0; mi < 4; mi++) {
        int r = m0 + mi * 16 + (lane & 15);
        int ch = (lane >> 4) * 8;
        aAddr[mi] = sbase + (r * SROW + ch) * 2;
    }
#pragma unroll
    for (int bj = 0; bj < 2; bj++) {
        int r = n0 + bj * 16 + (lane & 7) + ((lane >> 4) << 3);
        int ch = ((lane >> 3) & 1) * 8;
        bAddr[bj] = sbase + (128 * SROW + r * SROW + ch) * 2;
    }

    float acc[4][4][4];
#pragma unroll
    for (int mi = 0; mi < 4; mi++)
#pragma unroll
        for (int nj = 0; nj < 4; nj++)
#pragma unroll
            for (int q = 0; q < 4; q++) acc[mi][nj][q] = 0.f;

    for (int kt = 0; kt < 6; kt++) {
        if (kt) __syncthreads();
        int jt = kt >> 1;                 // token offset within window (0..2)
        int e0base = (kt & 1) * 128;      // element offset within token row
        for (int idx = tid; idx < 2048; idx += 256) {
            int rr = idx >> 4, c = idx & 15;
            int gr = row0 + rr;
            int p = gr / 510, t = gr - p * 510;
            int tok = path[p * Ln + t + jt];
            const float4* e4 = (const float4*)(embA + (size_t)tok * En + e0base + c * 8);
            float4 f0 = e4[0], f1 = e4[1];
            uint4 m4;
            m4.x = h2u(__floats2half2_rn(f0.x, f0.y));
            m4.y = h2u(__floats2half2_rn(f0.z, f0.w));
            m4.z = h2u(__floats2half2_rn(f1.x, f1.y));
            m4.w = h2u(__floats2half2_rn(f1.z, f1.w));
            *(uint4*)(As + rr * SROW + c * 8) = m4;
            const uint4* bsrc = (const uint4*)(g_cwh + (size_t)rr * 768 + kt * 128);
            *(uint4*)(Bs + rr * SROW + c * 8) = bsrc[c];
        }
        __syncthreads();

#pragma unroll
        for (int ks = 0; ks < 8; ks++) {
            unsigned a[4][4], b[2][4];
#pragma unroll
            for (int mi = 0; mi < 4; mi++)
                ldm_x4(a[mi][0], a[mi][1], a[mi][2], a[mi][3], aAddr[mi] + ks * 32);
#pragma unroll
            for (int bj = 0; bj < 2; bj++)
                ldm_x4(b[bj][0], b[bj][1], b[bj][2], b[bj][3], bAddr[bj] + ks * 32);
#pragma unroll
            for (int mi = 0; mi < 4; mi++)
#pragma unroll
                for (int nj = 0; nj < 4; nj++)
                    mma16816(acc[mi][nj], a[mi], b[nj >> 1][(nj & 1) * 2], b[nj >> 1][(nj & 1) * 2 + 1]);
        }
    }

    int qr = lane >> 2, qc = (lane & 3) * 2;
#pragma unroll
    for (int mi = 0; mi < 4; mi++) {
#pragma unroll
        for (int nj = 0; nj < 4; nj++) {
            int cc = n0 + nj * 8 + qc;
            float bx = bias_s[cc], by = bias_s[cc + 1];
            int r1 = row0 + m0 + mi * 16 + qr;
            __half2 v0 = __floats2half2_rn(fmaxf(acc[mi][nj][0] + bx, 0.f),
                                           fmaxf(acc[mi][nj][1] + by, 0.f));
            *(__half2*)(g_conv + (size_t)r1 * 128 + cc) = v0;
            __half2 v1 = __floats2half2_rn(fmaxf(acc[mi][nj][2] + bx, 0.f),
                                           fmaxf(acc[mi][nj][3] + by, 0.f));
            *(__half2*)(g_conv + (size_t)(r1 + 8) * 128 + cc) = v1;
        }
    }
}

// ---------------- launch 3: input-gate GEMM (pool fused, 2 col-tiles/CTA) -----
// grid (509, 4): CTA computes gx rows [row0,row0+128) x cols [by*256, by*256+256)
// A staged once; B double-buffered (Bs0/Bs1) -> one __syncthreads total.
__global__ void __launch_bounds__(256) gemm_kernel() {
    extern __shared__ __half smh[];
    __half* As  = smh;                 // [128 m][SROW]
    __half* Bs0 = smh + 128 * SROW;    // [128 n][SROW]
    __half* Bs1 = smh + 2 * 128 * SROW;
    __shared__ float bias_s[256];

    int row0    = blockIdx.x * 128;
    int colbase = blockIdx.y * 256;
    int tid  = threadIdx.x;
    int wid  = tid >> 5, lane = tid & 31;
    int m0 = (wid >> 2) * 64;
    int n0 = (wid & 3) * 32;

    bias_s[tid] = g_bias[colbase + tid];

    {
        const uint4* bsrc0 = (const uint4*)(g_wh + (size_t)colbase * 128);
        const uint4* bsrc1 = (const uint4*)(g_wh + (size_t)(colbase + 128) * 128);
        for (int idx = tid; idx < 2048; idx += 256) {
            int r = idx >> 4, c = idx & 15;
            int gr = row0 + r;
            int p = gr / Tn, t = gr - p * Tn;
            const uint4* csrc = (const uint4*)(g_conv + ((size_t)p * 510 + t) * 128);
            uint4 x = csrc[c], y = csrc[c + 16];
            UH2 ax, ay, r0, r1, r2, r3;
            ax.u = x.x; ay.u = y.x; r0.h = __hmax2(ax.h, ay.h);
            ax.u = x.y; ay.u = y.y; r1.h = __hmax2(ax.h, ay.h);
            ax.u = x.z; ay.u = y.z; r2.h = __hmax2(ax.h, ay.h);
            ax.u = x.w; ay.u = y.w; r3.h = __hmax2(ax.h, ay.h);
            uint4 m4 = make_uint4(r0.u, r1.u, r2.u, r3.u);
            *(uint4*)(As + r * SROW + c * 8) = m4;
            *(uint4*)(Bs0 + r * SROW + c * 8) = bsrc0[r * 16 + c];
            *(uint4*)(Bs1 + r * SROW + c * 8) = bsrc1[r * 16 + c];
        }
    }
    __syncthreads();

    unsigned sbase = (unsigned)__cvta_generic_to_shared(smh);
    unsigned aAddr[4], bAddr[2];
#pragma unroll
    for (int mi = 0; mi < 4; mi++) {
        int r = m0 + mi * 16 + (lane & 15);
        int ch = (lane >> 4) * 8;
        aAddr[mi] = sbase + (r * SROW + ch) * 2;
    }
#pragma unroll
    for (int bj = 0; bj < 2; bj++) {
        int r = n0 + bj * 16 + (lane & 7) + ((lane >> 4) << 3);
        int ch = ((lane >> 3) & 1) * 8;
        bAddr[bj] = sbase + (128 * SROW + r * SROW + ch) * 2;
    }

    int qr = lane >> 2, qc = (lane & 3) * 2;

#pragma unroll
    for (int cb = 0; cb < 2; cb++) {
        unsigned boff = cb * (128 * SROW * 2);   // bytes to Bs1
        float acc[4][4][4];
#pragma unroll
        for (int mi = 0; mi < 4; mi++)
#pragma unroll
            for (int nj = 0; nj < 4; nj++)
#pragma unroll
                for (int q = 0; q < 4; q++) acc[mi][nj][q] = 0.f;

#pragma unroll
        for (int ks = 0; ks < 8; ks++) {
            unsigned a[4][4], b[2][4];
#pragma unroll
            for (int mi = 0; mi < 4; mi++)
                ldm_x4(a[mi][0], a[mi][1], a[mi][2], a[mi][3], aAddr[mi] + ks * 32);
#pragma unroll
            for (int bj = 0; bj < 2; bj++)
                ldm_x4(b[bj][0], b[bj][1], b[bj][2], b[bj][3], bAddr[bj] + boff + ks * 32);
#pragma unroll
            for (int mi = 0; mi < 4; mi++)
#pragma unroll
                for (int nj = 0; nj < 4; nj++)
                    mma16816(acc[mi][nj], a[mi], b[nj >> 1][(nj & 1) * 2], b[nj >> 1][(nj & 1) * 2 + 1]);
        }

        int col0 = colbase + cb * 128;
#pragma unroll
        for (int mi = 0; mi < 4; mi++) {
#pragma unroll
            for (int nj = 0; nj < 4; nj++) {
                int cc = n0 + nj * 8 + qc;
                float bx = bias_s[cb * 128 + cc], by = bias_s[cb * 128 + cc + 1];
                size_t base = (size_t)(row0 + m0 + mi * 16 + qr) * 1024 + col0 + cc;
                *(__half2*)(g_gxh + base) = __floats2half2_rn(acc[mi][nj][0] + bx, acc[mi][nj][1] + by);
                *(__half2*)(g_gxh + base + 8 * 1024) = __floats2half2_rn(acc[mi][nj][2] + bx, acc[mi][nj][3] + by);
            }
        }
    }
}

// ---------------- launch 4: LSTM recurrence v5 (warp-local gates) -------------
// 128 CTAs: bid=(pg<<1)|dir, paths pg*2, pg*2+1; 256 threads (8 warps).
// Gate-interleaved A rows: warp w's 4 m-tiles = gates i,f,g,o of units
// [w*16, w*16+16). All preacts a warp needs are produced BY that warp ->
// redistribution is warp-private (512B smem patch + __syncwarp), and only
// ONE __syncthreads per step (hN publish; hN double-buffered).
__global__ void __launch_bounds__(256, 1) lstm_kernel(const float* __restrict__ whhf,
                                                      const float* __restrict__ whhb) {
    __shared__ float preW[8][4][16][2];              // per-warp patches, 4 KB
    __shared__ __align__(16) __half hN[2][8][136];   // [buf][path-slot][unit]

    int bid = blockIdx.x;
    int dir = bid & 1;
    int pg  = bid >> 1;
    int tid = threadIdx.x;
    int w   = tid >> 5, l = tid & 31;

    const float* whh = dir ? whhb : whhf;

    // A fragments: tile mt = gate mt of units [w*16, w*16+16)
    unsigned A[4][8][4];
#pragma unroll
    for (int mt = 0; mt < 4; mt++)
#pragma unroll
        for (int kc = 0; kc < 8; kc++) {
            int r = mt * 128 + w * 16 + (l >> 2);
            int k = kc * 16 + (l & 3) * 2;
            float2 v0 = *(const float2*)(whh + (size_t)r * 128 + k);
            float2 v1 = *(const float2*)(whh + (size_t)(r + 8) * 128 + k);
            float2 v2 = *(const float2*)(whh + (size_t)r * 128 + k + 8);
            float2 v3 = *(const float2*)(whh + (size_t)(r + 8) * 128 + k + 8);
            A[mt][kc][0] = h2u(__float22half2_rn(v0));
            A[mt][kc][1] = h2u(__float22half2_rn(v1));
            A[mt][kc][2] = h2u(__float22half2_rn(v2));
            A[mt][kc][3] = h2u(__float22half2_rn(v3));
        }

    // zero both hN buffers: 2*8*136 = 2176 halves = 1088 half2
    for (int i = tid; i < 1088; i += 256) ((__half2*)&hN[0][0][0])[i] = __float2half2_rn(0.f);

    // pointwise ownership: item (unit = w*16 + (l>>1), path = l&1)
    int ul = l >> 1, p = l & 1;
    int u  = w * 16 + ul;
    int pathg = pg * 2 + p;
    long stride = dir ? -1024 : 1024;
    const __half* gp = g_gxh + (size_t)pathg * Tn * 1024 + dir * 512 + u
                     + (dir ? (size_t)(Tn - 1) * 1024 : 0);
    float gi = __half2float(gp[0]),   gf = __half2float(gp[128]);
    float gg = __half2float(gp[256]), go = __half2float(gp[384]);

    float c = 0.f, hval = 0.f;
    unsigned sb = (unsigned)__cvta_generic_to_shared(&hN[0][0][0]);
    unsigned ldlane = ((l & 7) * 136 + (l >> 3) * 8) * 2;
    int strow = l >> 2;        // store row for lanes with (l&3)==0

    __syncthreads();

    for (int s = 0; s < Tn; s++) {
        int cb = s & 1;
        // prefetch next step's gx (overlaps MMA phase)
        const __half* gn = gp + ((s + 1 < Tn) ? stride : 0);
        float ni = __half2float(gn[0]),   nf = __half2float(gn[128]);
        float ng = __half2float(gn[256]), no_ = __half2float(gn[384]);

        unsigned b[8][2];
        unsigned ldbase = sb + cb * (8 * 136 * 2) + ldlane;
#pragma unroll
        for (int ks = 0; ks < 4; ks++) {
            unsigned r0, r1, r2, r3;
            ldm_x4(r0, r1, r2, r3, ldbase + ks * 64);
            b[2 * ks][0] = r0;     b[2 * ks][1] = r1;
            b[2 * ks + 1][0] = r2; b[2 * ks + 1][1] = r3;
        }
        // 4 independent depth-8 chains (one per gate tile)
        float C[4][4];
#pragma unroll
        for (int mt = 0; mt < 4; mt++) {
            C[mt][0] = 0.f; C[mt][1] = 0.f; C[mt][2] = 0.f; C[mt][3] = 0.f;
        }
#pragma unroll
        for (int kc = 0; kc < 8; kc++) {
#pragma unroll
            for (int mt = 0; mt < 4; mt++)
                mma16816(C[mt], A[mt][kc], b[kc][0], b[kc][1]);
        }

        // warp-private exchange: lanes holding cols 0-1 store; everyone reads
        if ((l & 3) == 0) {
#pragma unroll
            for (int mt = 0; mt < 4; mt++) {
                *(float2*)&preW[w][mt][strow][0]     = make_float2(C[mt][0], C[mt][1]);
                *(float2*)&preW[w][mt][strow + 8][0] = make_float2(C[mt][2], C[mt][3]);
            }
        }
        __syncwarp();

        float iv = siga (gi + preW[w][0][ul][p]);
        float fv = siga (gf + preW[w][1][ul][p]);
        float gv = tanha(gg + preW[w][2][ul][p]);
        float ov = siga (go + preW[w][3][ul][p]);
        c = fv * c + iv * gv;
        hval = ov * tanha(c);
        hN[cb ^ 1][p][u] = __float2half(hval);

        gi = ni; gf = nf; gg = ng; go = no_;
        gp = gn;
        __syncthreads();
    }
    g_ctx[pathg * 256 + dir * 128 + u] = hval;
}

// ---------------- attention --------------------------------------------------
__global__ void __launch_bounds__(256) att1_kernel(const float* __restrict__ d1b,
                                                   const float* __restrict__ d2w,
                                                   const float* __restrict__ d2b) {
    __shared__ float cat[512];
    __shared__ float red[256];
    int p = blockIdx.x, tid = threadIdx.x;
    cat[tid]       = g_ctx[p * 256 + tid];
    cat[256 + tid] = g_u[tid];
    __syncthreads();
    float acc = d1b[tid];
#pragma unroll 8
    for (int k = 0; k < 512; k++) acc += cat[k] * g_d1wT[k * 256 + tid];
    red[tid] = tanh_(acc) * d2w[tid];
    __syncthreads();
    for (int s = 128; s > 0; s >>= 1) {
        if (tid < s) red[tid] += red[tid + s];
        __syncthreads();
    }
    if (tid == 0) g_score[p] = red[0] + d2b[0];
}

__global__ void __launch_bounds__(256) att2_kernel(const float* __restrict__ d1b) {
    __shared__ float al[128];
    __shared__ float red[128];
    __shared__ float cat[512];
    int tid = threadIdx.x;
    cat[tid] = g_u[tid];
    if (tid < 128) red[tid] = g_score[tid];
    __syncthreads();
    for (int s = 64; s > 0; s >>= 1) {
        if (tid < s) red[tid] = fmaxf(red[tid], red[tid + s]);
        __syncthreads();
    }
    float m = red[0];
    __syncthreads();
    if (tid < 128) { float e = __expf(g_score[tid] - m); al[tid] = e; red[tid] = e; }
    __syncthreads();
    for (int s = 64; s > 0; s >>= 1) {
        if (tid < s) red[tid] += red[tid + s];
        __syncthreads();
    }
    float inv = __fdividef(1.f, red[0]);
    float o = 0.f;
#pragma unroll 8
    for (int p = 0; p < 128; p++) o += al[p] * g_ctx[p * 256 + tid];
    cat[256 + tid] = o * inv;
    __syncthreads();
    float acc = d1b[tid];
#pragma unroll 8
    for (int k = 0; k < 512; k++) acc += cat[k] * g_d1wT[k * 256 + tid];
    __syncthreads();
    g_u[tid] = acc;
}

__global__ void __launch_bounds__(256) final_kernel(const float* __restrict__ d2w,
                                                    const float* __restrict__ d2b,
                                                    float* __restrict__ out) {
    __shared__ float red[256];
    int tid = threadIdx.x;
    red[tid] = fmaxf(g_u[tid], 0.f) * d2w[tid];
    __syncthreads();
    for (int s = 128; s > 0; s >>= 1) {
        if (tid < s) red[tid] += red[tid + s];
        __syncthreads();
    }
    if (tid == 0) out[0] = __fdividef(1.f, 1.f + __expf(-(red[0] + d2b[0])));
}

// ---------------- launch ------------------------------------------------------
extern "C" void kernel_launch(void* const* d_in, const int* in_sizes, int n_in,
                              void* d_out, int out_size) {
    const int*   path   = (const int*)  d_in[0];
    const int*   query  = (const int*)  d_in[1];
    const float* embA   = (const float*)d_in[2];
    const float* embB   = (const float*)d_in[3];
    const float* conv_w = (const float*)d_in[4];
    const float* conv_b = (const float*)d_in[5];
    const float* wihf   = (const float*)d_in[6];
    const float* whhf   = (const float*)d_in[7];
    const float* bihf   = (const float*)d_in[8];
    const float* bhhf   = (const float*)d_in[9];
    const float* wihb   = (const float*)d_in[10];
    const float* whhb   = (const float*)d_in[11];
    const float* bihb   = (const float*)d_in[12];
    const float* bhhb   = (const float*)d_in[13];
    const float* d1w    = (const float*)d_in[14];
    const float* d1b    = (const float*)d_in[15];
    const float* d2w    = (const float*)d_in[16];
    const float* d2b    = (const float*)d_in[17];
    float* out = (float*)d_out;

    const int conv_smem = 2 * 128 * SROW * 2;          // 69632 B
    const int gemm_smem = 3 * 128 * SROW * 2;          // 104448 B
    cudaFuncSetAttribute(gemm_kernel, cudaFuncAttributeMaxDynamicSharedMemorySize, gemm_smem);
    cudaFuncSetAttribute(convgemm_kernel, cudaFuncAttributeMaxDynamicSharedMemorySize, conv_smem);

    setup_kernel<<<PREP_BLKS + 1, 256>>>(query, embB, conv_w, d1w,
                                         wihf, wihb, bihf, bhhf, bihb, bhhb);
    convgemm_kernel<<<510, 256, conv_smem>>>(path, embA, conv_b);
    gemm_kernel<<<dim3(509, 4), 256, gemm_smem>>>();
    lstm_kernel<<<128, 256>>>(whhf, whhb);
    for (int it = 0; it < 2; it++) {
        att1_kernel<<<128, 256>>>(d1b, d2w, d2b);
        att2_kernel<<<1, 256>>>(d1b);
    }
    final_kernel<<<1, 256>>>(d2w, d2b, out);
}

// round 13
// speedup vs baseline: 1.3050x; 1.0094x over previous
#include <cuda_runtime.h>
#include <cuda_fp16.h>
#include <math.h>

#define Pn 128
#define Ln 512
#define En 256
#define Fn 128
#define Tn 509
#define SROW 136   // padded halves per smem row (272 B: ldmatrix conflict-free)
#define WROW 264   // window row stride in halves (528 B: ldmatrix conflict-free)

// ---------------- scratch (device globals; allocation is forbidden) ----------
__device__ __half  g_conv[(size_t)Pn * 510 * Fn];  // conv+relu output [p][t'][f]
__device__ __half  g_gxh[(size_t)Pn * Tn * 1024];  // input gates fp16 [p*T][fwd512|bwd512]
__device__ float   g_ctx[Pn * En];                 // BiLSTM context [p][2H]
__device__ __half  g_cwh[Fn * 768];                // conv weights [f][w*256+e] fp16
__device__ float   g_d1wT[512 * 256];              // d1_w transposed [k][e]
__device__ __half  g_wh [1024 * 128];              // W_ih fp16 [n(fwd512|bwd512)][k]
__device__ float   g_bias[1024];                   // combined b_ih + b_hh
__device__ float   g_score[Pn];
__device__ float   g_u[En];

// ---------------- helpers ----------------------------------------------------
__device__ __forceinline__ float sigf(float x) {
    return __fdividef(1.f, 1.f + __expf(-x));
}
__device__ __forceinline__ float tanh_(float x) {
    return __fdividef(2.f, 1.f + __expf(-2.f * x)) - 1.f;
}
__device__ __forceinline__ float tanha(float x) {
    float y;
    asm("tanh.approx.f32 %0, %1;" : "=f"(y) : "f"(x));
    return y;
}
__device__ __forceinline__ float siga(float x) {
    return fmaf(0.5f, tanha(0.5f * x), 0.5f);
}
union UH2 { unsigned int u; __half2 h; };
__device__ __forceinline__ unsigned h2u(__half2 h) { UH2 v; v.h = h; return v.u; }
__device__ __forceinline__ __half2 u2h(unsigned x) { UH2 v; v.u = x; return v.h; }

__device__ __forceinline__ void ldm_x4(unsigned& r0, unsigned& r1, unsigned& r2, unsigned& r3,
                                       unsigned addr) {
    asm volatile("ldmatrix.sync.aligned.m8n8.x4.shared.b16 {%0,%1,%2,%3}, [%4];"
                 : "=r"(r0), "=r"(r1), "=r"(r2), "=r"(r3) : "r"(addr));
}
__device__ __forceinline__ void mma16816(float* c, const unsigned* a, unsigned b0, unsigned b1) {
    asm volatile("mma.sync.aligned.m16n8k16.row.col.f32.f16.f16.f32 "
                 "{%0,%1,%2,%3}, {%4,%5,%6,%7}, {%8,%9}, {%0,%1,%2,%3};"
                 : "+f"(c[0]), "+f"(c[1]), "+f"(c[2]), "+f"(c[3])
                 : "r"(a[0]), "r"(a[1]), "r"(a[2]), "r"(a[3]), "r"(b0), "r"(b1));
}

// ---------------- launch 1: setupA (cwh + d1wT) -------------------------------
__global__ void __launch_bounds__(256) setupA_kernel(const float* __restrict__ conv_w,
                                                     const float* __restrict__ d1w) {
    int idx = blockIdx.x * 256 + threadIdx.x;
    if (idx < 98304) {                        // cwh[f][w*256+e] = conv_w[f][e][w]
        int f = idx / 768, r = idx - f * 768;
        int w = r >> 8, e = r & 255;
        g_cwh[idx] = __float2half(conv_w[(size_t)f * 768 + e * 3 + w]);
    } else if (idx < 98304 + 131072) {        // d1wT[k*256+e]
        int j = idx - 98304;
        int e = j & 255, k = j >> 8;
        g_d1wT[j] = d1w[(size_t)e * 512 + k];
    }
}

// ---------------- launch 2: setupB (wh + bias + init_u) -----------------------
__global__ void __launch_bounds__(256) setupB_kernel(
        const int* __restrict__ query, const float* __restrict__ embB,
        const float* __restrict__ wihf, const float* __restrict__ wihb,
        const float* __restrict__ bihf, const float* __restrict__ bhhf,
        const float* __restrict__ bihb, const float* __restrict__ bhhb) {
    int idx = blockIdx.x * 256 + threadIdx.x;
    if (idx < 131072) {                       // g_wh[n][k] fp16
        int k = idx & 127, n = idx >> 7;
        float w = (n < 512) ? wihf[(size_t)n * 128 + k] : wihb[(size_t)(n - 512) * 128 + k];
        g_wh[idx] = __float2half(w);
    } else if (idx < 131072 + 1024) {         // g_bias[n]
        int n = idx - 131072;
        g_bias[n] = (n < 512) ? (bihf[n] + bhhf[n]) : (bihb[n - 512] + bhhb[n - 512]);
    } else if (idx < 131072 + 1024 + 256) {   // init u
        int t = idx - 132096;
        g_u[t] = embB[(size_t)query[0] * En + t];
    }
}

// ---------------- launch 3: conv as GEMM (smem token window) ------------------
// Window: 132 token embeddings (fp16, WROW stride) staged once per CTA;
// ldmatrix A-fragments read DIRECTLY from the window (no As staging).
// Per-lane row offset +2 corrects the (at most one) path-boundary crossing.
__global__ void __launch_bounds__(256) convgemm_kernel(const int* __restrict__ path,
                                                       const float* __restrict__ embA,
                                                       const float* __restrict__ conv_b) {
    extern __shared__ __half smh[];
    __half* win = smh;                  // [132][WROW]
    __half* Bs  = smh + 132 * WROW;     // [128 f][SROW]
    __shared__ float bias_s[128];

    int row0 = blockIdx.x * 128;
    int tid  = threadIdx.x;
    int wid  = tid >> 5, lane = tid & 31;
    int m0 = (wid >> 2) * 64;
    int n0 = (wid & 3) * 32;

    int p0 = row0 / 510;
    int t0 = row0 - 510 * p0;

    if (tid < 128) bias_s[tid] = conv_b[tid];

    // fill token window: row i = embedding of conv-row (row0+i)'s window start,
    // linearized in same-path-extended token space (see offrow correction).
    for (int idx = tid; idx < 132 * 32; idx += 256) {
        int i = idx >> 5, c = idx & 31;
        int ti = t0 + i;
        int tok;
        if (ti < 512) {
            tok = path[p0 * Ln + ti];
        } else {
            int p1 = (p0 + 1 < Pn) ? p0 + 1 : p0;
            tok = path[p1 * Ln + (ti - 512)];
        }
        const float4* e4 = (const float4*)(embA + (size_t)tok * En + c * 8);
        float4 f0 = e4[0], f1 = e4[1];
        uint4 m4;
        m4.x = h2u(__floats2half2_rn(f0.x, f0.y));
        m4.y = h2u(__floats2half2_rn(f0.z, f0.w));
        m4.z = h2u(__floats2half2_rn(f1.x, f1.y));
        m4.w = h2u(__floats2half2_rn(f1.z, f1.w));
        *(uint4*)(win + i * WROW + c * 8) = m4;
    }

    unsigned sbase = (unsigned)__cvta_generic_to_shared(smh);
    unsigned aAddr[4], bAddr[2];
#pragma unroll
    for (int mi = 0; mi < 4; mi++) {
        int r = m0 + mi * 16 + (lane & 15);
        int off = ((t0 + r) >= 510) ? 2 : 0;     // crossed path boundary
        int ch = (lane >> 4) * 8;
        aAddr[mi] = sbase + (((r + off) * WROW) + ch) * 2;
    }
#pragma unroll
    for (int bj = 0; bj < 2; bj++) {
        int r = n0 + bj * 16 + (lane & 7) + ((lane >> 4) << 3);
        int ch = ((lane >> 3) & 1) * 8;
        bAddr[bj] = sbase + 132 * WROW * 2 + (r * SROW + ch) * 2;
    }

    float acc[4][4][4];
#pragma unroll
    for (int mi = 0; mi < 4; mi++)
#pragma unroll
        for (int nj = 0; nj < 4; nj++)
#pragma unroll
            for (int q = 0; q < 4; q++) acc[mi][nj][q] = 0.f;

    for (int kt = 0; kt < 6; kt++) {
        if (kt) __syncthreads();             // prior MMA done before Bs overwrite
        for (int idx = tid; idx < 2048; idx += 256) {
            int rr = idx >> 4, c = idx & 15;
            const uint4* bsrc = (const uint4*)(g_cwh + (size_t)rr * 768 + kt * 128);
            *(uint4*)(Bs + rr * SROW + c * 8) = bsrc[c];
        }
        __syncthreads();                     // window (kt==0) + Bs ready

        int jt = kt >> 1;
        int e0 = (kt & 1) * 128;
        unsigned aoff = (jt * WROW + e0) * 2;
#pragma unroll
        for (int ks = 0; ks < 8; ks++) {
            unsigned a[4][4], b[2][4];
#pragma unroll
            for (int mi = 0; mi < 4; mi++)
                ldm_x4(a[mi][0], a[mi][1], a[mi][2], a[mi][3], aAddr[mi] + aoff + ks * 32);
#pragma unroll
            for (int bj = 0; bj < 2; bj++)
                ldm_x4(b[bj][0], b[bj][1], b[bj][2], b[bj][3], bAddr[bj] + ks * 32);
#pragma unroll
            for (int mi = 0; mi < 4; mi++)
#pragma unroll
                for (int nj = 0; nj < 4; nj++)
                    mma16816(acc[mi][nj], a[mi], b[nj >> 1][(nj & 1) * 2], b[nj >> 1][(nj & 1) * 2 + 1]);
        }
    }

    int qr = lane >> 2, qc = (lane & 3) * 2;
#pragma unroll
    for (int mi = 0; mi < 4; mi++) {
#pragma unroll
        for (int nj = 0; nj < 4; nj++) {
            int cc = n0 + nj * 8 + qc;
            float bx = bias_s[cc], by = bias_s[cc + 1];
            int r1 = row0 + m0 + mi * 16 + qr;
            __half2 v0 = __floats2half2_rn(fmaxf(acc[mi][nj][0] + bx, 0.f),
                                           fmaxf(acc[mi][nj][1] + by, 0.f));
            *(__half2*)(g_conv + (size_t)r1 * 128 + cc) = v0;
            __half2 v1 = __floats2half2_rn(fmaxf(acc[mi][nj][2] + bx, 0.f),
                                           fmaxf(acc[mi][nj][3] + by, 0.f));
            *(__half2*)(g_conv + (size_t)(r1 + 8) * 128 + cc) = v1;
        }
    }
}

// ---------------- launch 4 (PROFILED): input-gate GEMM ------------------------
// grid (509, 4): CTA computes gx rows [row0,row0+128) x cols [by*256, by*256+256)
__global__ void __launch_bounds__(256) gemm_kernel() {
    extern __shared__ __half smh[];
    __half* As  = smh;                 // [128 m][SROW]
    __half* Bs0 = smh + 128 * SROW;    // [128 n][SROW]
    __half* Bs1 = smh + 2 * 128 * SROW;
    __shared__ float bias_s[256];

    int row0    = blockIdx.x * 128;
    int colbase = blockIdx.y * 256;
    int tid  = threadIdx.x;
    int wid  = tid >> 5, lane = tid & 31;
    int m0 = (wid >> 2) * 64;
    int n0 = (wid & 3) * 32;

    bias_s[tid] = g_bias[colbase + tid];

    {
        const uint4* bsrc0 = (const uint4*)(g_wh + (size_t)colbase * 128);
        const uint4* bsrc1 = (const uint4*)(g_wh + (size_t)(colbase + 128) * 128);
        for (int idx = tid; idx < 2048; idx += 256) {
            int r = idx >> 4, c = idx & 15;
            int gr = row0 + r;
            int p = gr / Tn, t = gr - p * Tn;
            const uint4* csrc = (const uint4*)(g_conv + ((size_t)p * 510 + t) * 128);
            uint4 x = csrc[c], y = csrc[c + 16];
            UH2 ax, ay, r0, r1, r2, r3;
            ax.u = x.x; ay.u = y.x; r0.h = __hmax2(ax.h, ay.h);
            ax.u = x.y; ay.u = y.y; r1.h = __hmax2(ax.h, ay.h);
            ax.u = x.z; ay.u = y.z; r2.h = __hmax2(ax.h, ay.h);
            ax.u = x.w; ay.u = y.w; r3.h = __hmax2(ax.h, ay.h);
            uint4 m4 = make_uint4(r0.u, r1.u, r2.u, r3.u);
            *(uint4*)(As + r * SROW + c * 8) = m4;
            *(uint4*)(Bs0 + r * SROW + c * 8) = bsrc0[r * 16 + c];
            *(uint4*)(Bs1 + r * SROW + c * 8) = bsrc1[r * 16 + c];
        }
    }
    __syncthreads();

    unsigned sbase = (unsigned)__cvta_generic_to_shared(smh);
    unsigned aAddr[4], bAddr[2];
#pragma unroll
    for (int mi = 0; mi < 4; mi++) {
        int r = m0 + mi * 16 + (lane & 15);
        int ch = (lane >> 4) * 8;
        aAddr[mi] = sbase + (r * SROW + ch) * 2;
    }
#pragma unroll
    for (int bj = 0; bj < 2; bj++) {
        int r = n0 + bj * 16 + (lane & 7) + ((lane >> 4) << 3);
        int ch = ((lane >> 3) & 1) * 8;
        bAddr[bj] = sbase + (128 * SROW + r * SROW + ch) * 2;
    }

    int qr = lane >> 2, qc = (lane & 3) * 2;

#pragma unroll
    for (int cb = 0; cb < 2; cb++) {
        unsigned boff = cb * (128 * SROW * 2);
        float acc[4][4][4];
#pragma unroll
        for (int mi = 0; mi < 4; mi++)
#pragma unroll
            for (int nj = 0; nj < 4; nj++)
#pragma unroll
                for (int q = 0; q < 4; q++) acc[mi][nj][q] = 0.f;

#pragma unroll
        for (int ks = 0; ks < 8; ks++) {
            unsigned a[4][4], b[2][4];
#pragma unroll
            for (int mi = 0; mi < 4; mi++)
                ldm_x4(a[mi][0], a[mi][1], a[mi][2], a[mi][3], aAddr[mi] + ks * 32);
#pragma unroll
            for (int bj = 0; bj < 2; bj++)
                ldm_x4(b[bj][0], b[bj][1], b[bj][2], b[bj][3], bAddr[bj] + boff + ks * 32);
#pragma unroll
            for (int mi = 0; mi < 4; mi++)
#pragma unroll
                for (int nj = 0; nj < 4; nj++)
                    mma16816(acc[mi][nj], a[mi], b[nj >> 1][(nj & 1) * 2], b[nj >> 1][(nj & 1) * 2 + 1]);
        }

        int col0 = colbase + cb * 128;
#pragma unroll
        for (int mi = 0; mi < 4; mi++) {
#pragma unroll
            for (int nj = 0; nj < 4; nj++) {
                int cc = n0 + nj * 8 + qc;
                float bx = bias_s[cb * 128 + cc], by = bias_s[cb * 128 + cc + 1];
                size_t base = (size_t)(row0 + m0 + mi * 16 + qr) * 1024 + col0 + cc;
                *(__half2*)(g_gxh + base) = __floats2half2_rn(acc[mi][nj][0] + bx, acc[mi][nj][1] + by);
                *(__half2*)(g_gxh + base + 8 * 1024) = __floats2half2_rn(acc[mi][nj][2] + bx, acc[mi][nj][3] + by);
            }
        }
    }
}

// ---------------- launch 5: LSTM recurrence v5 (warp-local gates) -------------
__global__ void __launch_bounds__(256, 1) lstm_kernel(const float* __restrict__ whhf,
                                                      const float* __restrict__ whhb) {
    __shared__ float preW[8][4][16][2];              // per-warp patches, 4 KB
    __shared__ __align__(16) __half hN[2][8][136];   // [buf][path-slot][unit]

    int bid = blockIdx.x;
    int dir = bid & 1;
    int pg  = bid >> 1;
    int tid = threadIdx.x;
    int w   = tid >> 5, l = tid & 31;

    const float* whh = dir ? whhb : whhf;

    unsigned A[4][8][4];
#pragma unroll
    for (int mt = 0; mt < 4; mt++)
#pragma unroll
        for (int kc = 0; kc < 8; kc++) {
            int r = mt * 128 + w * 16 + (l >> 2);
            int k = kc * 16 + (l & 3) * 2;
            float2 v0 = *(const float2*)(whh + (size_t)r * 128 + k);
            float2 v1 = *(const float2*)(whh + (size_t)(r + 8) * 128 + k);
            float2 v2 = *(const float2*)(whh + (size_t)r * 128 + k + 8);
            float2 v3 = *(const float2*)(whh + (size_t)(r + 8) * 128 + k + 8);
            A[mt][kc][0] = h2u(__float22half2_rn(v0));
            A[mt][kc][1] = h2u(__float22half2_rn(v1));
            A[mt][kc][2] = h2u(__float22half2_rn(v2));
            A[mt][kc][3] = h2u(__float22half2_rn(v3));
        }

    for (int i = tid; i < 1088; i += 256) ((__half2*)&hN[0][0][0])[i] = __float2half2_rn(0.f);

    int ul = l >> 1, p = l & 1;
    int u  = w * 16 + ul;
    int pathg = pg * 2 + p;
    long stride = dir ? -1024 : 1024;
    const __half* gp = g_gxh + (size_t)pathg * Tn * 1024 + dir * 512 + u
                     + (dir ? (size_t)(Tn - 1) * 1024 : 0);
    float gi = __half2float(gp[0]),   gf = __half2float(gp[128]);
    float gg = __half2float(gp[256]), go = __half2float(gp[384]);

    float c = 0.f, hval = 0.f;
    unsigned sb = (unsigned)__cvta_generic_to_shared(&hN[0][0][0]);
    unsigned ldlane = ((l & 7) * 136 + (l >> 3) * 8) * 2;
    int strow = l >> 2;

    __syncthreads();

    for (int s = 0; s < Tn; s++) {
        int cb = s & 1;
        const __half* gn = gp + ((s + 1 < Tn) ? stride : 0);
        float ni = __half2float(gn[0]),   nf = __half2float(gn[128]);
        float ng = __half2float(gn[256]), no_ = __half2float(gn[384]);

        unsigned b[8][2];
        unsigned ldbase = sb + cb * (8 * 136 * 2) + ldlane;
#pragma unroll
        for (int ks = 0; ks < 4; ks++) {
            unsigned r0, r1, r2, r3;
            ldm_x4(r0, r1, r2, r3, ldbase + ks * 64);
            b[2 * ks][0] = r0;     b[2 * ks][1] = r1;
            b[2 * ks + 1][0] = r2; b[2 * ks + 1][1] = r3;
        }
        float C[4][4];
#pragma unroll
        for (int mt = 0; mt < 4; mt++) {
            C[mt][0] = 0.f; C[mt][1] = 0.f; C[mt][2] = 0.f; C[mt][3] = 0.f;
        }
#pragma unroll
        for (int kc = 0; kc < 8; kc++) {
#pragma unroll
            for (int mt = 0; mt < 4; mt++)
                mma16816(C[mt], A[mt][kc], b[kc][0], b[kc][1]);
        }

        if ((l & 3) == 0) {
#pragma unroll
            for (int mt = 0; mt < 4; mt++) {
                *(float2*)&preW[w][mt][strow][0]     = make_float2(C[mt][0], C[mt][1]);
                *(float2*)&preW[w][mt][strow + 8][0] = make_float2(C[mt][2], C[mt][3]);
            }
        }
        __syncwarp();

        float iv = siga (gi + preW[w][0][ul][p]);
        float fv = siga (gf + preW[w][1][ul][p]);
        float gv = tanha(gg + preW[w][2][ul][p]);
        float ov = siga (go + preW[w][3][ul][p]);
        c = fv * c + iv * gv;
        hval = ov * tanha(c);
        hN[cb ^ 1][p][u] = __float2half(hval);

        gi = ni; gf = nf; gg = ng; go = no_;
        gp = gn;
        __syncthreads();
    }
    g_ctx[pathg * 256 + dir * 128 + u] = hval;
}

// ---------------- attention --------------------------------------------------
__global__ void __launch_bounds__(256) att1_kernel(const float* __restrict__ d1b,
                                                   const float* __restrict__ d2w,
                                                   const float* __restrict__ d2b) {
    __shared__ float cat[512];
    __shared__ float red[256];
    int p = blockIdx.x, tid = threadIdx.x;
    cat[tid]       = g_ctx[p * 256 + tid];
    cat[256 + tid] = g_u[tid];
    __syncthreads();
    float acc = d1b[tid];
#pragma unroll 8
    for (int k = 0; k < 512; k++) acc += cat[k] * g_d1wT[k * 256 + tid];
    red[tid] = tanh_(acc) * d2w[tid];
    __syncthreads();
    for (int s = 128; s > 0; s >>= 1) {
        if (tid < s) red[tid] += red[tid + s];
        __syncthreads();
    }
    if (tid == 0) g_score[p] = red[0] + d2b[0];
}

// att2 with optional fused final head (last==1 on the 2nd iteration)
__global__ void __launch_bounds__(256) att2_kernel(const float* __restrict__ d1b,
                                                   const float* __restrict__ d2w,
                                                   const float* __restrict__ d2b,
                                                   float* __restrict__ out, int last) {
    __shared__ float al[128];
    __shared__ float red[128];
    __shared__ float cat[512];
    int tid = threadIdx.x;
    cat[tid] = g_u[tid];
    if (tid < 128) red[tid] = g_score[tid];
    __syncthreads();
    for (int s = 64; s > 0; s >>= 1) {
        if (tid < s) red[tid] = fmaxf(red[tid], red[tid + s]);
        __syncthreads();
    }
    float m = red[0];
    __syncthreads();
    if (tid < 128) { float e = __expf(g_score[tid] - m); al[tid] = e; red[tid] = e; }
    __syncthreads();
    for (int s = 64; s > 0; s >>= 1) {
        if (tid < s) red[tid] += red[tid + s];
        __syncthreads();
    }
    float inv = __fdividef(1.f, red[0]);
    float o = 0.f;
#pragma unroll 8
    for (int p = 0; p < 128; p++) o += al[p] * g_ctx[p * 256 + tid];
    cat[256 + tid] = o * inv;
    __syncthreads();
    float acc = d1b[tid];
#pragma unroll 8
    for (int k = 0; k < 512; k++) acc += cat[k] * g_d1wT[k * 256 + tid];
    __syncthreads();
    if (!last) {
        g_u[tid] = acc;
    } else {
        // fused final head: relu(u) . d2w -> sigmoid
        cat[tid] = fmaxf(acc, 0.f) * d2w[tid];
        __syncthreads();
        for (int s = 128; s > 0; s >>= 1) {
            if (tid < s) cat[tid] += cat[tid + s];
            __syncthreads();
        }
        if (tid == 0) out[0] = __fdividef(1.f, 1.f + __expf(-(cat[0] + d2b[0])));
    }
}

// ---------------- launch ------------------------------------------------------
extern "C" void kernel_launch(void* const* d_in, const int* in_sizes, int n_in,
                              void* d_out, int out_size) {
    const int*   path   = (const int*)  d_in[0];
    const int*   query  = (const int*)  d_in[1];
    const float* embA   = (const float*)d_in[2];
    const float* embB   = (const float*)d_in[3];
    const float* conv_w = (const float*)d_in[4];
    const float* conv_b = (const float*)d_in[5];
    const float* wihf   = (const float*)d_in[6];
    const float* whhf   = (const float*)d_in[7];
    const float* bihf   = (const float*)d_in[8];
    const float* bhhf   = (const float*)d_in[9];
    const float* wihb   = (const float*)d_in[10];
    const float* whhb   = (const float*)d_in[11];
    const float* bihb   = (const float*)d_in[12];
    const float* bhhb   = (const float*)d_in[13];
    const float* d1w    = (const float*)d_in[14];
    const float* d1b    = (const float*)d_in[15];
    const float* d2w    = (const float*)d_in[16];
    const float* d2b    = (const float*)d_in[17];
    float* out = (float*)d_out;

    const int conv_smem = (132 * WROW + 128 * SROW) * 2;   // 104512 B
    const int gemm_smem = 3 * 128 * SROW * 2;              // 104448 B
    cudaFuncSetAttribute(gemm_kernel, cudaFuncAttributeMaxDynamicSharedMemorySize, gemm_smem);
    cudaFuncSetAttribute(convgemm_kernel, cudaFuncAttributeMaxDynamicSharedMemorySize, conv_smem);

    setupA_kernel<<<896, 256>>>(conv_w, d1w);
    setupB_kernel<<<518, 256>>>(query, embB, wihf, wihb, bihf, bhhf, bihb, bhhb);
    convgemm_kernel<<<510, 256, conv_smem>>>(path, embA, conv_b);
    gemm_kernel<<<dim3(509, 4), 256, gemm_smem>>>();
    lstm_kernel<<<128, 256>>>(whhf, whhb);
    att1_kernel<<<128, 256>>>(d1b, d2w, d2b);
    att2_kernel<<<1, 256>>>(d1b, d2w, d2b, out, 0);
    att1_kernel<<<128, 256>>>(d1b, d2w, d2b);
    att2_kernel<<<1, 256>>>(d1b, d2w, d2b, out, 1);
}

// round 14
// speedup vs baseline: 1.3226x; 1.0135x over previous
#include <cuda_runtime.h>
#include <cuda_fp16.h>
#include <math.h>

#define Pn 128
#define Ln 512
#define En 256
#define Fn 128
#define Tn 509
#define SROW 136   // padded halves per smem row (272 B: ldmatrix conflict-free)
#define WROW 264   // window row stride in halves (528 B: ldmatrix conflict-free)

// ---------------- scratch (device globals; allocation is forbidden) ----------
__device__ __half  g_conv[(size_t)Pn * 510 * Fn];  // conv+relu output [p][t'][f]
__device__ __half  g_gxh[(size_t)Pn * Tn * 1024];  // input gates fp16 [p*T][fwd512|bwd512]
__device__ float   g_ctx[Pn * En];                 // BiLSTM context [p][2H]
__device__ __half  g_cwh[Fn * 768];                // conv weights [f][w*256+e] fp16
__device__ float   g_d1wT[512 * 256];              // d1_w transposed [k][e]
__device__ __half  g_wh [1024 * 128];              // W_ih fp16 [n(fwd512|bwd512)][k]
__device__ float   g_bias[1024];                   // combined b_ih + b_hh
__device__ float   g_score[Pn];
__device__ float   g_u[En];

// ---------------- helpers ----------------------------------------------------
__device__ __forceinline__ float sigf(float x) {
    return __fdividef(1.f, 1.f + __expf(-x));
}
__device__ __forceinline__ float tanh_(float x) {
    return __fdividef(2.f, 1.f + __expf(-2.f * x)) - 1.f;
}
__device__ __forceinline__ float tanha(float x) {
    float y;
    asm("tanh.approx.f32 %0, %1;" : "=f"(y) : "f"(x));
    return y;
}
__device__ __forceinline__ float siga(float x) {
    return fmaf(0.5f, tanha(0.5f * x), 0.5f);
}
union UH2 { unsigned int u; __half2 h; };
__device__ __forceinline__ unsigned h2u(__half2 h) { UH2 v; v.h = h; return v.u; }
__device__ __forceinline__ __half2 u2h(unsigned x) { UH2 v; v.u = x; return v.h; }

__device__ __forceinline__ void ldm_x4(unsigned& r0, unsigned& r1, unsigned& r2, unsigned& r3,
                                       unsigned addr) {
    asm volatile("ldmatrix.sync.aligned.m8n8.x4.shared.b16 {%0,%1,%2,%3}, [%4];"
                 : "=r"(r0), "=r"(r1), "=r"(r2), "=r"(r3) : "r"(addr));
}
__device__ __forceinline__ void mma16816(float* c, const unsigned* a, unsigned b0, unsigned b1) {
    asm volatile("mma.sync.aligned.m16n8k16.row.col.f32.f16.f16.f32 "
                 "{%0,%1,%2,%3}, {%4,%5,%6,%7}, {%8,%9}, {%0,%1,%2,%3};"
                 : "+f"(c[0]), "+f"(c[1]), "+f"(c[2]), "+f"(c[3])
                 : "r"(a[0]), "r"(a[1]), "r"(a[2]), "r"(a[3]), "r"(b0), "r"(b1));
}

// ---------------- launch 1: setupA (cwh + d1wT) -------------------------------
__global__ void __launch_bounds__(256) setupA_kernel(const float* __restrict__ conv_w,
                                                     const float* __restrict__ d1w) {
    int idx = blockIdx.x * 256 + threadIdx.x;
    if (idx < 98304) {                        // cwh[f][w*256+e] = conv_w[f][e][w]
        int f = idx / 768, r = idx - f * 768;
        int w = r >> 8, e = r & 255;
        g_cwh[idx] = __float2half(conv_w[(size_t)f * 768 + e * 3 + w]);
    } else if (idx < 98304 + 131072) {        // d1wT[k*256+e]
        int j = idx - 98304;
        int e = j & 255, k = j >> 8;
        g_d1wT[j] = d1w[(size_t)e * 512 + k];
    }
}

// ---------------- launch 2: setupB (wh + bias + init_u) -----------------------
__global__ void __launch_bounds__(256) setupB_kernel(
        const int* __restrict__ query, const float* __restrict__ embB,
        const float* __restrict__ wihf, const float* __restrict__ wihb,
        const float* __restrict__ bihf, const float* __restrict__ bhhf,
        const float* __restrict__ bihb, const float* __restrict__ bhhb) {
    int idx = blockIdx.x * 256 + threadIdx.x;
    if (idx < 131072) {                       // g_wh[n][k] fp16
        int k = idx & 127, n = idx >> 7;
        float w = (n < 512) ? wihf[(size_t)n * 128 + k] : wihb[(size_t)(n - 512) * 128 + k];
        g_wh[idx] = __float2half(w);
    } else if (idx < 131072 + 1024) {         // g_bias[n]
        int n = idx - 131072;
        g_bias[n] = (n < 512) ? (bihf[n] + bhhf[n]) : (bihb[n - 512] + bhhb[n - 512]);
    } else if (idx < 131072 + 1024 + 256) {   // init u
        int t = idx - 132096;
        g_u[t] = embB[(size_t)query[0] * En + t];
    }
}

// ---------------- launch 3: conv as GEMM (smem token window) ------------------
__global__ void __launch_bounds__(256) convgemm_kernel(const int* __restrict__ path,
                                                       const float* __restrict__ embA,
                                                       const float* __restrict__ conv_b) {
    extern __shared__ __half smh[];
    __half* win = smh;                  // [132][WROW]
    __half* Bs  = smh + 132 * WROW;     // [128 f][SROW]
    __shared__ float bias_s[128];

    int row0 = blockIdx.x * 128;
    int tid  = threadIdx.x;
    int wid  = tid >> 5, lane = tid & 31;
    int m0 = (wid >> 2) * 64;
    int n0 = (wid & 3) * 32;

    int p0 = row0 / 510;
    int t0 = row0 - 510 * p0;

    if (tid < 128) bias_s[tid] = conv_b[tid];

    for (int idx = tid; idx < 132 * 32; idx += 256) {
        int i = idx >> 5, c = idx & 31;
        int ti = t0 + i;
        int tok;
        if (ti < 512) {
            tok = path[p0 * Ln + ti];
        } else {
            int p1 = (p0 + 1 < Pn) ? p0 + 1 : p0;
            tok = path[p1 * Ln + (ti - 512)];
        }
        const float4* e4 = (const float4*)(embA + (size_t)tok * En + c * 8);
        float4 f0 = e4[0], f1 = e4[1];
        uint4 m4;
        m4.x = h2u(__floats2half2_rn(f0.x, f0.y));
        m4.y = h2u(__floats2half2_rn(f0.z, f0.w));
        m4.z = h2u(__floats2half2_rn(f1.x, f1.y));
        m4.w = h2u(__floats2half2_rn(f1.z, f1.w));
        *(uint4*)(win + i * WROW + c * 8) = m4;
    }

    unsigned sbase = (unsigned)__cvta_generic_to_shared(smh);
    unsigned aAddr[4], bAddr[2];
#pragma unroll
    for (int mi = 0; mi < 4; mi++) {
        int r = m0 + mi * 16 + (lane & 15);
        int off = ((t0 + r) >= 510) ? 2 : 0;     // crossed path boundary
        int ch = (lane >> 4) * 8;
        aAddr[mi] = sbase + (((r + off) * WROW) + ch) * 2;
    }
#pragma unroll
    for (int bj = 0; bj < 2; bj++) {
        int r = n0 + bj * 16 + (lane & 7) + ((lane >> 4) << 3);
        int ch = ((lane >> 3) & 1) * 8;
        bAddr[bj] = sbase + 132 * WROW * 2 + (r * SROW + ch) * 2;
    }

    float acc[4][4][4];
#pragma unroll
    for (int mi = 0; mi < 4; mi++)
#pragma unroll
        for (int nj = 0; nj < 4; nj++)
#pragma unroll
            for (int q = 0; q < 4; q++) acc[mi][nj][q] = 0.f;

    for (int kt = 0; kt < 6; kt++) {
        if (kt) __syncthreads();
        for (int idx = tid; idx < 2048; idx += 256) {
            int rr = idx >> 4, c = idx & 15;
            const uint4* bsrc = (const uint4*)(g_cwh + (size_t)rr * 768 + kt * 128);
            *(uint4*)(Bs + rr * SROW + c * 8) = bsrc[c];
        }
        __syncthreads();

        int jt = kt >> 1;
        int e0 = (kt & 1) * 128;
        unsigned aoff = (jt * WROW + e0) * 2;
#pragma unroll
        for (int ks = 0; ks < 8; ks++) {
            unsigned a[4][4], b[2][4];
#pragma unroll
            for (int mi = 0; mi < 4; mi++)
                ldm_x4(a[mi][0], a[mi][1], a[mi][2], a[mi][3], aAddr[mi] + aoff + ks * 32);
#pragma unroll
            for (int bj = 0; bj < 2; bj++)
                ldm_x4(b[bj][0], b[bj][1], b[bj][2], b[bj][3], bAddr[bj] + ks * 32);
#pragma unroll
            for (int mi = 0; mi < 4; mi++)
#pragma unroll
                for (int nj = 0; nj < 4; nj++)
                    mma16816(acc[mi][nj], a[mi], b[nj >> 1][(nj & 1) * 2], b[nj >> 1][(nj & 1) * 2 + 1]);
        }
    }

    int qr = lane >> 2, qc = (lane & 3) * 2;
#pragma unroll
    for (int mi = 0; mi < 4; mi++) {
#pragma unroll
        for (int nj = 0; nj < 4; nj++) {
            int cc = n0 + nj * 8 + qc;
            float bx = bias_s[cc], by = bias_s[cc + 1];
            int r1 = row0 + m0 + mi * 16 + qr;
            __half2 v0 = __floats2half2_rn(fmaxf(acc[mi][nj][0] + bx, 0.f),
                                           fmaxf(acc[mi][nj][1] + by, 0.f));
            *(__half2*)(g_conv + (size_t)r1 * 128 + cc) = v0;
            __half2 v1 = __floats2half2_rn(fmaxf(acc[mi][nj][2] + bx, 0.f),
                                           fmaxf(acc[mi][nj][3] + by, 0.f));
            *(__half2*)(g_conv + (size_t)(r1 + 8) * 128 + cc) = v1;
        }
    }
}

// ---------------- launch 4 (PROFILED): input-gate GEMM (R11 topology) ---------
// grid (509, 8): single 128x128 col-tile/CTA, 69.6 KB smem -> 2 CTAs/SM.
__global__ void __launch_bounds__(256) gemm_kernel() {
    extern __shared__ __half smh[];
    __half* As = smh;                 // [128 m][SROW]
    __half* Bs = smh + 128 * SROW;    // [128 n][SROW]
    __shared__ float bias_s[128];

    int row0 = blockIdx.x * 128;
    int col0 = blockIdx.y * 128;
    int tid  = threadIdx.x;
    int wid  = tid >> 5, lane = tid & 31;
    int m0 = (wid >> 2) * 64;
    int n0 = (wid & 3) * 32;

    if (tid < 128) bias_s[tid] = g_bias[col0 + tid];

    {
        const uint4* bsrc = (const uint4*)(g_wh + (size_t)col0 * 128);
        for (int idx = tid; idx < 2048; idx += 256) {
            int r = idx >> 4, c = idx & 15;
            int gr = row0 + r;
            int p = gr / Tn, t = gr - p * Tn;
            const uint4* csrc = (const uint4*)(g_conv + ((size_t)p * 510 + t) * 128);
            uint4 x = csrc[c], y = csrc[c + 16];
            UH2 ax, ay, r0, r1, r2, r3;
            ax.u = x.x; ay.u = y.x; r0.h = __hmax2(ax.h, ay.h);
            ax.u = x.y; ay.u = y.y; r1.h = __hmax2(ax.h, ay.h);
            ax.u = x.z; ay.u = y.z; r2.h = __hmax2(ax.h, ay.h);
            ax.u = x.w; ay.u = y.w; r3.h = __hmax2(ax.h, ay.h);
            uint4 m4 = make_uint4(r0.u, r1.u, r2.u, r3.u);
            *(uint4*)(As + r * SROW + c * 8) = m4;
            *(uint4*)(Bs + r * SROW + c * 8) = bsrc[r * 16 + c];
        }
    }
    __syncthreads();

    unsigned sbase = (unsigned)__cvta_generic_to_shared(smh);
    unsigned aAddr[4], bAddr[2];
#pragma unroll
    for (int mi = 0; mi < 4; mi++) {
        int r = m0 + mi * 16 + (lane & 15);
        int ch = (lane >> 4) * 8;
        aAddr[mi] = sbase + (r * SROW + ch) * 2;
    }
#pragma unroll
    for (int bj = 0; bj < 2; bj++) {
        int r = n0 + bj * 16 + (lane & 7) + ((lane >> 4) << 3);
        int ch = ((lane >> 3) & 1) * 8;
        bAddr[bj] = sbase + (128 * SROW + r * SROW + ch) * 2;
    }

    float acc[4][4][4];
#pragma unroll
    for (int mi = 0; mi < 4; mi++)
#pragma unroll
        for (int nj = 0; nj < 4; nj++)
#pragma unroll
            for (int q = 0; q < 4; q++) acc[mi][nj][q] = 0.f;

#pragma unroll
    for (int ks = 0; ks < 8; ks++) {
        unsigned a[4][4], b[2][4];
#pragma unroll
        for (int mi = 0; mi < 4; mi++)
            ldm_x4(a[mi][0], a[mi][1], a[mi][2], a[mi][3], aAddr[mi] + ks * 32);
#pragma unroll
        for (int bj = 0; bj < 2; bj++)
            ldm_x4(b[bj][0], b[bj][1], b[bj][2], b[bj][3], bAddr[bj] + ks * 32);
#pragma unroll
        for (int mi = 0; mi < 4; mi++)
#pragma unroll
            for (int nj = 0; nj < 4; nj++)
                mma16816(acc[mi][nj], a[mi], b[nj >> 1][(nj & 1) * 2], b[nj >> 1][(nj & 1) * 2 + 1]);
    }

    int qr = lane >> 2, qc = (lane & 3) * 2;
#pragma unroll
    for (int mi = 0; mi < 4; mi++) {
#pragma unroll
        for (int nj = 0; nj < 4; nj++) {
            int cc = n0 + nj * 8 + qc;
            float bx = bias_s[cc], by = bias_s[cc + 1];
            size_t base = (size_t)(row0 + m0 + mi * 16 + qr) * 1024 + col0 + cc;
            *(__half2*)(g_gxh + base) = __floats2half2_rn(acc[mi][nj][0] + bx, acc[mi][nj][1] + by);
            *(__half2*)(g_gxh + base + 8 * 1024) = __floats2half2_rn(acc[mi][nj][2] + bx, acc[mi][nj][3] + by);
        }
    }
}

// ---------------- launch 5: LSTM recurrence v5 (warp-local gates) -------------
__global__ void __launch_bounds__(256, 1) lstm_kernel(const float* __restrict__ whhf,
                                                      const float* __restrict__ whhb) {
    __shared__ float preW[8][4][16][2];              // per-warp patches, 4 KB
    __shared__ __align__(16) __half hN[2][8][136];   // [buf][path-slot][unit]

    int bid = blockIdx.x;
    int dir = bid & 1;
    int pg  = bid >> 1;
    int tid = threadIdx.x;
    int w   = tid >> 5, l = tid & 31;

    const float* whh = dir ? whhb : whhf;

    unsigned A[4][8][4];
#pragma unroll
    for (int mt = 0; mt < 4; mt++)
#pragma unroll
        for (int kc = 0; kc < 8; kc++) {
            int r = mt * 128 + w * 16 + (l >> 2);
            int k = kc * 16 + (l & 3) * 2;
            float2 v0 = *(const float2*)(whh + (size_t)r * 128 + k);
            float2 v1 = *(const float2*)(whh + (size_t)(r + 8) * 128 + k);
            float2 v2 = *(const float2*)(whh + (size_t)r * 128 + k + 8);
            float2 v3 = *(const float2*)(whh + (size_t)(r + 8) * 128 + k + 8);
            A[mt][kc][0] = h2u(__float22half2_rn(v0));
            A[mt][kc][1] = h2u(__float22half2_rn(v1));
            A[mt][kc][2] = h2u(__float22half2_rn(v2));
            A[mt][kc][3] = h2u(__float22half2_rn(v3));
        }

    for (int i = tid; i < 1088; i += 256) ((__half2*)&hN[0][0][0])[i] = __float2half2_rn(0.f);

    int ul = l >> 1, p = l & 1;
    int u  = w * 16 + ul;
    int pathg = pg * 2 + p;
    long stride = dir ? -1024 : 1024;
    const __half* gp = g_gxh + (size_t)pathg * Tn * 1024 + dir * 512 + u
                     + (dir ? (size_t)(Tn - 1) * 1024 : 0);
    float gi = __half2float(gp[0]),   gf = __half2float(gp[128]);
    float gg = __half2float(gp[256]), go = __half2float(gp[384]);

    float c = 0.f, hval = 0.f;
    unsigned sb = (unsigned)__cvta_generic_to_shared(&hN[0][0][0]);
    unsigned ldlane = ((l & 7) * 136 + (l >> 3) * 8) * 2;
    int strow = l >> 2;

    __syncthreads();

    for (int s = 0; s < Tn; s++) {
        int cb = s & 1;
        const __half* gn = gp + ((s + 1 < Tn) ? stride : 0);
        float ni = __half2float(gn[0]),   nf = __half2float(gn[128]);
        float ng = __half2float(gn[256]), no_ = __half2float(gn[384]);

        unsigned b[8][2];
        unsigned ldbase = sb + cb * (8 * 136 * 2) + ldlane;
#pragma unroll
        for (int ks = 0; ks < 4; ks++) {
            unsigned r0, r1, r2, r3;
            ldm_x4(r0, r1, r2, r3, ldbase + ks * 64);
            b[2 * ks][0] = r0;     b[2 * ks][1] = r1;
            b[2 * ks + 1][0] = r2; b[2 * ks + 1][1] = r3;
        }
        float C[4][4];
#pragma unroll
        for (int mt = 0; mt < 4; mt++) {
            C[mt][0] = 0.f; C[mt][1] = 0.f; C[mt][2] = 0.f; C[mt][3] = 0.f;
        }
#pragma unroll
        for (int kc = 0; kc < 8; kc++) {
#pragma unroll
            for (int mt = 0; mt < 4; mt++)
                mma16816(C[mt], A[mt][kc], b[kc][0], b[kc][1]);
        }

        if ((l & 3) == 0) {
#pragma unroll
            for (int mt = 0; mt < 4; mt++) {
                *(float2*)&preW[w][mt][strow][0]     = make_float2(C[mt][0], C[mt][1]);
                *(float2*)&preW[w][mt][strow + 8][0] = make_float2(C[mt][2], C[mt][3]);
            }
        }
        __syncwarp();

        float iv = siga (gi + preW[w][0][ul][p]);
        float fv = siga (gf + preW[w][1][ul][p]);
        float gv = tanha(gg + preW[w][2][ul][p]);
        float ov = siga (go + preW[w][3][ul][p]);
        c = fv * c + iv * gv;
        hval = ov * tanha(c);
        hN[cb ^ 1][p][u] = __float2half(hval);

        gi = ni; gf = nf; gg = ng; go = no_;
        gp = gn;
        __syncthreads();
    }
    g_ctx[pathg * 256 + dir * 128 + u] = hval;
}

// ---------------- attention --------------------------------------------------
__global__ void __launch_bounds__(256) att1_kernel(const float* __restrict__ d1b,
                                                   const float* __restrict__ d2w,
                                                   const float* __restrict__ d2b) {
    __shared__ float cat[512];
    __shared__ float red[256];
    int p = blockIdx.x, tid = threadIdx.x;
    cat[tid]       = g_ctx[p * 256 + tid];
    cat[256 + tid] = g_u[tid];
    __syncthreads();
    float acc = d1b[tid];
#pragma unroll 8
    for (int k = 0; k < 512; k++) acc += cat[k] * g_d1wT[k * 256 + tid];
    red[tid] = tanh_(acc) * d2w[tid];
    __syncthreads();
    for (int s = 128; s > 0; s >>= 1) {
        if (tid < s) red[tid] += red[tid + s];
        __syncthreads();
    }
    if (tid == 0) g_score[p] = red[0] + d2b[0];
}

// att2 with optional fused final head (last==1 on the 2nd iteration)
__global__ void __launch_bounds__(256) att2_kernel(const float* __restrict__ d1b,
                                                   const float* __restrict__ d2w,
                                                   const float* __restrict__ d2b,
                                                   float* __restrict__ out, int last) {
    __shared__ float al[128];
    __shared__ float red[128];
    __shared__ float cat[512];
    int tid = threadIdx.x;
    cat[tid] = g_u[tid];
    if (tid < 128) red[tid] = g_score[tid];
    __syncthreads();
    for (int s = 64; s > 0; s >>= 1) {
        if (tid < s) red[tid] = fmaxf(red[tid], red[tid + s]);
        __syncthreads();
    }
    float m = red[0];
    __syncthreads();
    if (tid < 128) { float e = __expf(g_score[tid] - m); al[tid] = e; red[tid] = e; }
    __syncthreads();
    for (int s = 64; s > 0; s >>= 1) {
        if (tid < s) red[tid] += red[tid + s];
        __syncthreads();
    }
    float inv = __fdividef(1.f, red[0]);
    float o = 0.f;
#pragma unroll 8
    for (int p = 0; p < 128; p++) o += al[p] * g_ctx[p * 256 + tid];
    cat[256 + tid] = o * inv;
    __syncthreads();
    float acc = d1b[tid];
#pragma unroll 8
    for (int k = 0; k < 512; k++) acc += cat[k] * g_d1wT[k * 256 + tid];
    __syncthreads();
    if (!last) {
        g_u[tid] = acc;
    } else {
        cat[tid] = fmaxf(acc, 0.f) * d2w[tid];
        __syncthreads();
        for (int s = 128; s > 0; s >>= 1) {
            if (tid < s) cat[tid] += cat[tid + s];
            __syncthreads();
        }
        if (tid == 0) out[0] = __fdividef(1.f, 1.f + __expf(-(cat[0] + d2b[0])));
    }
}

// ---------------- launch ------------------------------------------------------
extern "C" void kernel_launch(void* const* d_in, const int* in_sizes, int n_in,
                              void* d_out, int out_size) {
    const int*   path   = (const int*)  d_in[0];
    const int*   query  = (const int*)  d_in[1];
    const float* embA   = (const float*)d_in[2];
    const float* embB   = (const float*)d_in[3];
    const float* conv_w = (const float*)d_in[4];
    const float* conv_b = (const float*)d_in[5];
    const float* wihf   = (const float*)d_in[6];
    const float* whhf   = (const float*)d_in[7];
    const float* bihf   = (const float*)d_in[8];
    const float* bhhf   = (const float*)d_in[9];
    const float* wihb   = (const float*)d_in[10];
    const float* whhb   = (const float*)d_in[11];
    const float* bihb   = (const float*)d_in[12];
    const float* bhhb   = (const float*)d_in[13];
    const float* d1w    = (const float*)d_in[14];
    const float* d1b    = (const float*)d_in[15];
    const float* d2w    = (const float*)d_in[16];
    const float* d2b    = (const float*)d_in[17];
    float* out = (float*)d_out;

    const int conv_smem = (132 * WROW + 128 * SROW) * 2;   // 104512 B
    const int gemm_smem = 2 * 128 * SROW * 2;              // 69632 B -> 2 CTAs/SM
    cudaFuncSetAttribute(gemm_kernel, cudaFuncAttributeMaxDynamicSharedMemorySize, gemm_smem);
    cudaFuncSetAttribute(convgemm_kernel, cudaFuncAttributeMaxDynamicSharedMemorySize, conv_smem);

    setupA_kernel<<<896, 256>>>(conv_w, d1w);
    setupB_kernel<<<518, 256>>>(query, embB, wihf, wihb, bihf, bhhf, bihb, bhhb);
    convgemm_kernel<<<510, 256, conv_smem>>>(path, embA, conv_b);
    gemm_kernel<<<dim3(509, 8), 256, gemm_smem>>>();
    lstm_kernel<<<128, 256>>>(whhf, whhb);
    att1_kernel<<<128, 256>>>(d1b, d2w, d2b);
    att2_kernel<<<1, 256>>>(d1b, d2w, d2b, out, 0);
    att1_kernel<<<128, 256>>>(d1b, d2w, d2b);
    att2_kernel<<<1, 256>>>(d1b, d2w, d2b, out, 1);
}

// round 15
// speedup vs baseline: 1.3536x; 1.0234x over previous
#include <cuda_runtime.h>
#include <cuda_fp16.h>
#include <math.h>

#define Pn 128
#define Ln 512
#define En 256
#define Fn 128
#define Tn 509
#define SROW 136   // padded halves per smem row (272 B: ldmatrix conflict-free)
#define WROW 264   // window row stride in halves (528 B: ldmatrix conflict-free)

// ---------------- scratch (device globals; allocation is forbidden) ----------
__device__ __half  g_conv[(size_t)Pn * 510 * Fn];  // conv+relu output [p][t'][f]
__device__ __half  g_xsh[(size_t)Pn * Tn * Fn];    // pooled conv output [p*Tn+t][f]
__device__ __half  g_gxh[(size_t)Pn * Tn * 1024];  // input gates fp16 [p*T][fwd512|bwd512]
__device__ float   g_ctx[Pn * En];                 // BiLSTM context [p][2H]
__device__ __half  g_cwh[Fn * 768];                // conv weights [f][w*256+e] fp16
__device__ float   g_d1wT[512 * 256];              // d1_w transposed [k][e]
__device__ __half  g_wh [1024 * 128];              // W_ih fp16 [n(fwd512|bwd512)][k]
__device__ float   g_bias[1024];                   // combined b_ih + b_hh
__device__ float   g_score[Pn];
__device__ float   g_u[En];

// ---------------- helpers ----------------------------------------------------
__device__ __forceinline__ float sigf(float x) {
    return __fdividef(1.f, 1.f + __expf(-x));
}
__device__ __forceinline__ float tanh_(float x) {
    return __fdividef(2.f, 1.f + __expf(-2.f * x)) - 1.f;
}
__device__ __forceinline__ float tanha(float x) {
    float y;
    asm("tanh.approx.f32 %0, %1;" : "=f"(y) : "f"(x));
    return y;
}
__device__ __forceinline__ float siga(float x) {
    return fmaf(0.5f, tanha(0.5f * x), 0.5f);
}
union UH2 { unsigned int u; __half2 h; };
__device__ __forceinline__ unsigned h2u(__half2 h) { UH2 v; v.h = h; return v.u; }
__device__ __forceinline__ __half2 u2h(unsigned x) { UH2 v; v.u = x; return v.h; }

__device__ __forceinline__ void ldm_x4(unsigned& r0, unsigned& r1, unsigned& r2, unsigned& r3,
                                       unsigned addr) {
    asm volatile("ldmatrix.sync.aligned.m8n8.x4.shared.b16 {%0,%1,%2,%3}, [%4];"
                 : "=r"(r0), "=r"(r1), "=r"(r2), "=r"(r3) : "r"(addr));
}
__device__ __forceinline__ void mma16816(float* c, const unsigned* a, unsigned b0, unsigned b1) {
    asm volatile("mma.sync.aligned.m16n8k16.row.col.f32.f16.f16.f32 "
                 "{%0,%1,%2,%3}, {%4,%5,%6,%7}, {%8,%9}, {%0,%1,%2,%3};"
                 : "+f"(c[0]), "+f"(c[1]), "+f"(c[2]), "+f"(c[3])
                 : "r"(a[0]), "r"(a[1]), "r"(a[2]), "r"(a[3]), "r"(b0), "r"(b1));
}
__device__ __forceinline__ void cpasync16(unsigned dst, const void* src) {
    asm volatile("cp.async.cg.shared.global [%0], [%1], 16;" :: "r"(dst), "l"(src));
}
__device__ __forceinline__ void cp_commit() { asm volatile("cp.async.commit_group;" ::: "memory"); }
__device__ __forceinline__ void cp_wait1() { asm volatile("cp.async.wait_group 1;" ::: "memory"); }
__device__ __forceinline__ void cp_wait0() { asm volatile("cp.async.wait_group 0;" ::: "memory"); }

// ---------------- launch 1: setup (prep + init_u) -----------------------------
#define PREP_BLKS 1412
__global__ void __launch_bounds__(256) setup_kernel(
        const int* __restrict__ query, const float* __restrict__ embB,
        const float* __restrict__ conv_w, const float* __restrict__ d1w,
        const float* __restrict__ wihf, const float* __restrict__ wihb,
        const float* __restrict__ bihf, const float* __restrict__ bhhf,
        const float* __restrict__ bihb, const float* __restrict__ bhhb) {
    int bx = blockIdx.x;
    if (bx < PREP_BLKS) {
        int idx = bx * 256 + threadIdx.x;
        if (idx < 98304) {                        // cwh[f][w*256+e] = conv_w[f][e][w]
            int f = idx / 768, r = idx - f * 768;
            int w = r >> 8, e = r & 255;
            g_cwh[idx] = __float2half(conv_w[(size_t)f * 768 + e * 3 + w]);
        } else if (idx < 98304 + 131072) {        // d1wT[k*256+e]
            int j = idx - 98304;
            int e = j & 255, k = j >> 8;
            g_d1wT[j] = d1w[(size_t)e * 512 + k];
        } else if (idx < 229376 + 131072) {       // g_wh[n][k] fp16
            int j = idx - 229376;
            int k = j & 127, n = j >> 7;
            float w = (n < 512) ? wihf[(size_t)n * 128 + k] : wihb[(size_t)(n - 512) * 128 + k];
            g_wh[j] = __float2half(w);
        } else if (idx < 360448 + 1024) {         // g_bias[n]
            int n = idx - 360448;
            g_bias[n] = (n < 512) ? (bihf[n] + bhhf[n]) : (bihb[n - 512] + bhhb[n - 512]);
        }
    } else {
        g_u[threadIdx.x] = embB[(size_t)query[0] * En + threadIdx.x];
    }
}

// ---------------- launch 2: conv as GEMM (smem token window) ------------------
__global__ void __launch_bounds__(256) convgemm_kernel(const int* __restrict__ path,
                                                       const float* __restrict__ embA,
                                                       const float* __restrict__ conv_b) {
    extern __shared__ __half smh[];
    __half* win = smh;                  // [132][WROW]
    __half* Bs  = smh + 132 * WROW;     // [128 f][SROW]
    __shared__ float bias_s[128];

    int row0 = blockIdx.x * 128;
    int tid  = threadIdx.x;
    int wid  = tid >> 5, lane = tid & 31;
    int m0 = (wid >> 2) * 64;
    int n0 = (wid & 3) * 32;

    int p0 = row0 / 510;
    int t0 = row0 - 510 * p0;

    if (tid < 128) bias_s[tid] = conv_b[tid];

    for (int idx = tid; idx < 132 * 32; idx += 256) {
        int i = idx >> 5, c = idx & 31;
        int ti = t0 + i;
        int tok;
        if (ti < 512) {
            tok = path[p0 * Ln + ti];
        } else {
            int p1 = (p0 + 1 < Pn) ? p0 + 1 : p0;
            tok = path[p1 * Ln + (ti - 512)];
        }
        const float4* e4 = (const float4*)(embA + (size_t)tok * En + c * 8);
        float4 f0 = e4[0], f1 = e4[1];
        uint4 m4;
        m4.x = h2u(__floats2half2_rn(f0.x, f0.y));
        m4.y = h2u(__floats2half2_rn(f0.z, f0.w));
        m4.z = h2u(__floats2half2_rn(f1.x, f1.y));
        m4.w = h2u(__floats2half2_rn(f1.z, f1.w));
        *(uint4*)(win + i * WROW + c * 8) = m4;
    }

    unsigned sbase = (unsigned)__cvta_generic_to_shared(smh);
    unsigned aAddr[4], bAddr[2];
#pragma unroll
    for (int mi = 0; mi < 4; mi++) {
        int r = m0 + mi * 16 + (lane & 15);
        int off = ((t0 + r) >= 510) ? 2 : 0;     // crossed path boundary
        int ch = (lane >> 4) * 8;
        aAddr[mi] = sbase + (((r + off) * WROW) + ch) * 2;
    }
#pragma unroll
    for (int bj = 0; bj < 2; bj++) {
        int r = n0 + bj * 16 + (lane & 7) + ((lane >> 4) << 3);
        int ch = ((lane >> 3) & 1) * 8;
        bAddr[bj] = sbase + 132 * WROW * 2 + (r * SROW + ch) * 2;
    }

    float acc[4][4][4];
#pragma unroll
    for (int mi = 0; mi < 4; mi++)
#pragma unroll
        for (int nj = 0; nj < 4; nj++)
#pragma unroll
            for (int q = 0; q < 4; q++) acc[mi][nj][q] = 0.f;

    for (int kt = 0; kt < 6; kt++) {
        if (kt) __syncthreads();
        for (int idx = tid; idx < 2048; idx += 256) {
            int rr = idx >> 4, c = idx & 15;
            const uint4* bsrc = (const uint4*)(g_cwh + (size_t)rr * 768 + kt * 128);
            *(uint4*)(Bs + rr * SROW + c * 8) = bsrc[c];
        }
        __syncthreads();

        int jt = kt >> 1;
        int e0 = (kt & 1) * 128;
        unsigned aoff = (jt * WROW + e0) * 2;
#pragma unroll
        for (int ks = 0; ks < 8; ks++) {
            unsigned a[4][4], b[2][4];
#pragma unroll
            for (int mi = 0; mi < 4; mi++)
                ldm_x4(a[mi][0], a[mi][1], a[mi][2], a[mi][3], aAddr[mi] + aoff + ks * 32);
#pragma unroll
            for (int bj = 0; bj < 2; bj++)
                ldm_x4(b[bj][0], b[bj][1], b[bj][2], b[bj][3], bAddr[bj] + ks * 32);
#pragma unroll
            for (int mi = 0; mi < 4; mi++)
#pragma unroll
                for (int nj = 0; nj < 4; nj++)
                    mma16816(acc[mi][nj], a[mi], b[nj >> 1][(nj & 1) * 2], b[nj >> 1][(nj & 1) * 2 + 1]);
        }
    }

    int qr = lane >> 2, qc = (lane & 3) * 2;
#pragma unroll
    for (int mi = 0; mi < 4; mi++) {
#pragma unroll
        for (int nj = 0; nj < 4; nj++) {
            int cc = n0 + nj * 8 + qc;
            float bx = bias_s[cc], by = bias_s[cc + 1];
            int r1 = row0 + m0 + mi * 16 + qr;
            __half2 v0 = __floats2half2_rn(fmaxf(acc[mi][nj][0] + bx, 0.f),
                                           fmaxf(acc[mi][nj][1] + by, 0.f));
            *(__half2*)(g_conv + (size_t)r1 * 128 + cc) = v0;
            __half2 v1 = __floats2half2_rn(fmaxf(acc[mi][nj][2] + bx, 0.f),
                                           fmaxf(acc[mi][nj][3] + by, 0.f));
            *(__half2*)(g_conv + (size_t)(r1 + 8) * 128 + cc) = v1;
        }
    }
}

// ---------------- launch 3: maxpool(2, stride 1) ------------------------------
__global__ void __launch_bounds__(256) pool_kernel() {
    int idx = blockIdx.x * blockDim.x + threadIdx.x;   // over Pn*Tn*64 half2
    if (idx >= Pn * Tn * 64) return;
    int c2 = idx & 63;
    int r  = idx >> 6;            // p*Tn + t
    int p  = r / Tn, t = r - p * Tn;
    const __half2* src = (const __half2*)g_conv + ((size_t)p * 510 + t) * 64 + c2;
    ((__half2*)g_xsh)[(size_t)r * 64 + c2] = __hmax2(src[0], src[64]);
}

// ---------------- launch 4 (PROFILED): persistent input-gate GEMM -------------
// grid (8 cols, 64): CTA owns col block by (B loaded ONCE), loops 8 row-tiles
// with cp.async double-buffered A. smem = Bs + 2*As = 104448 B -> 2 CTAs/SM.
__global__ void __launch_bounds__(256) gemm_kernel() {
    extern __shared__ __half smh[];
    // layout: Bs [128][SROW] at 0; As0 at 128*SROW; As1 at 2*128*SROW
    __half* Bs = smh;
    __shared__ float bias_s[128];

    int by  = blockIdx.x;             // 0..7
    int gy  = blockIdx.y;             // 0..63
    int col0 = by * 128;
    int tid  = threadIdx.x;
    int wid  = tid >> 5, lane = tid & 31;
    int m0 = (wid >> 2) * 64;
    int n0 = (wid & 3) * 32;

    if (tid < 128) bias_s[tid] = g_bias[col0 + tid];

    // load B once
    {
        const uint4* bsrc = (const uint4*)(g_wh + (size_t)col0 * 128);
        for (int idx = tid; idx < 2048; idx += 256) {
            int r = idx >> 4, c = idx & 15;
            *(uint4*)(Bs + r * SROW + c * 8) = bsrc[r * 16 + c];
        }
    }

    unsigned sbase = (unsigned)__cvta_generic_to_shared(smh);
    const unsigned aBuf[2] = { (unsigned)(128 * SROW * 2), (unsigned)(2 * 128 * SROW * 2) };

    // per-thread cp.async lane pattern (8 chunks of 16 B)
    unsigned cpDst[8];
    int cpR[8], cpC[8];
#pragma unroll
    for (int j = 0; j < 8; j++) {
        int idx = tid + j * 256;
        cpR[j] = idx >> 4; cpC[j] = idx & 15;
        cpDst[j] = (unsigned)((cpR[j] * SROW + cpC[j] * 8) * 2);
    }

    // fragment lane offsets (bytes)
    unsigned aLane[4], bAddr[2];
#pragma unroll
    for (int mi = 0; mi < 4; mi++) {
        int r = m0 + mi * 16 + (lane & 15);
        int ch = (lane >> 4) * 8;
        aLane[mi] = (unsigned)((r * SROW + ch) * 2);
    }
#pragma unroll
    for (int bj = 0; bj < 2; bj++) {
        int r = n0 + bj * 16 + (lane & 7) + ((lane >> 4) << 3);
        int ch = ((lane >> 3) & 1) * 8;
        bAddr[bj] = sbase + (unsigned)((r * SROW + ch) * 2);
    }

    int tr0 = gy * 8;
    int ntiles = 509 - tr0; if (ntiles > 8) ntiles = 8;

    // issue tile 0 into buffer 0
    {
        const __half* asrc = g_xsh + (size_t)tr0 * 128 * 128;
#pragma unroll
        for (int j = 0; j < 8; j++)
            cpasync16(sbase + aBuf[0] + cpDst[j], asrc + cpR[j] * 128 + cpC[j] * 8);
        cp_commit();
    }

    int qr = lane >> 2, qc = (lane & 3) * 2;

    for (int i = 0; i < ntiles; i++) {
        int buf = i & 1;
        if (i + 1 < ntiles) {
            const __half* asrc = g_xsh + (size_t)(tr0 + i + 1) * 128 * 128;
#pragma unroll
            for (int j = 0; j < 8; j++)
                cpasync16(sbase + aBuf[buf ^ 1] + cpDst[j], asrc + cpR[j] * 128 + cpC[j] * 8);
            cp_commit();
            cp_wait1();
        } else {
            cp_wait0();
        }
        __syncthreads();   // buffer i full for all warps (also: B on i==0)

        float acc[4][4][4];
#pragma unroll
        for (int mi = 0; mi < 4; mi++)
#pragma unroll
            for (int nj = 0; nj < 4; nj++)
#pragma unroll
                for (int q = 0; q < 4; q++) acc[mi][nj][q] = 0.f;

        unsigned abase = sbase + aBuf[buf];
#pragma unroll
        for (int ks = 0; ks < 8; ks++) {
            unsigned a[4][4], b[2][4];
#pragma unroll
            for (int mi = 0; mi < 4; mi++)
                ldm_x4(a[mi][0], a[mi][1], a[mi][2], a[mi][3], abase + aLane[mi] + ks * 32);
#pragma unroll
            for (int bj = 0; bj < 2; bj++)
                ldm_x4(b[bj][0], b[bj][1], b[bj][2], b[bj][3], bAddr[bj] + ks * 32);
#pragma unroll
            for (int mi = 0; mi < 4; mi++)
#pragma unroll
                for (int nj = 0; nj < 4; nj++)
                    mma16816(acc[mi][nj], a[mi], b[nj >> 1][(nj & 1) * 2], b[nj >> 1][(nj & 1) * 2 + 1]);
        }

        int row0 = (tr0 + i) * 128;
#pragma unroll
        for (int mi = 0; mi < 4; mi++) {
#pragma unroll
            for (int nj = 0; nj < 4; nj++) {
                int cc = n0 + nj * 8 + qc;
                float bx = bias_s[cc], by_ = bias_s[cc + 1];
                size_t base = (size_t)(row0 + m0 + mi * 16 + qr) * 1024 + col0 + cc;
                *(__half2*)(g_gxh + base) = __floats2half2_rn(acc[mi][nj][0] + bx, acc[mi][nj][1] + by_);
                *(__half2*)(g_gxh + base + 8 * 1024) = __floats2half2_rn(acc[mi][nj][2] + bx, acc[mi][nj][3] + by_);
            }
        }
        __syncthreads();   // all reads of buffer i done before it is refilled
    }
}

// ---------------- launch 5: LSTM recurrence v5 (warp-local gates) -------------
__global__ void __launch_bounds__(256, 1) lstm_kernel(const float* __restrict__ whhf,
                                                      const float* __restrict__ whhb) {
    __shared__ float preW[8][4][16][2];              // per-warp patches, 4 KB
    __shared__ __align__(16) __half hN[2][8][136];   // [buf][path-slot][unit]

    int bid = blockIdx.x;
    int dir = bid & 1;
    int pg  = bid >> 1;
    int tid = threadIdx.x;
    int w   = tid >> 5, l = tid & 31;

    const float* whh = dir ? whhb : whhf;

    unsigned A[4][8][4];
#pragma unroll
    for (int mt = 0; mt < 4; mt++)
#pragma unroll
        for (int kc = 0; kc < 8; kc++) {
            int r = mt * 128 + w * 16 + (l >> 2);
            int k = kc * 16 + (l & 3) * 2;
            float2 v0 = *(const float2*)(whh + (size_t)r * 128 + k);
            float2 v1 = *(const float2*)(whh + (size_t)(r + 8) * 128 + k);
            float2 v2 = *(const float2*)(whh + (size_t)r * 128 + k + 8);
            float2 v3 = *(const float2*)(whh + (size_t)(r + 8) * 128 + k + 8);
            A[mt][kc][0] = h2u(__float22half2_rn(v0));
            A[mt][kc][1] = h2u(__float22half2_rn(v1));
            A[mt][kc][2] = h2u(__float22half2_rn(v2));
            A[mt][kc][3] = h2u(__float22half2_rn(v3));
        }

    for (int i = tid; i < 1088; i += 256) ((__half2*)&hN[0][0][0])[i] = __float2half2_rn(0.f);

    int ul = l >> 1, p = l & 1;
    int u  = w * 16 + ul;
    int pathg = pg * 2 + p;
    long stride = dir ? -1024 : 1024;
    const __half* gp = g_gxh + (size_t)pathg * Tn * 1024 + dir * 512 + u
                     + (dir ? (size_t)(Tn - 1) * 1024 : 0);
    float gi = __half2float(gp[0]),   gf = __half2float(gp[128]);
    float gg = __half2float(gp[256]), go = __half2float(gp[384]);

    float c = 0.f, hval = 0.f;
    unsigned sb = (unsigned)__cvta_generic_to_shared(&hN[0][0][0]);
    unsigned ldlane = ((l & 7) * 136 + (l >> 3) * 8) * 2;
    int strow = l >> 2;

    __syncthreads();

    for (int s = 0; s < Tn; s++) {
        int cb = s & 1;
        const __half* gn = gp + ((s + 1 < Tn) ? stride : 0);
        float ni = __half2float(gn[0]),   nf = __half2float(gn[128]);
        float ng = __half2float(gn[256]), no_ = __half2float(gn[384]);

        unsigned b[8][2];
        unsigned ldbase = sb + cb * (8 * 136 * 2) + ldlane;
#pragma unroll
        for (int ks = 0; ks < 4; ks++) {
            unsigned r0, r1, r2, r3;
            ldm_x4(r0, r1, r2, r3, ldbase + ks * 64);
            b[2 * ks][0] = r0;     b[2 * ks][1] = r1;
            b[2 * ks + 1][0] = r2; b[2 * ks + 1][1] = r3;
        }
        float C[4][4];
#pragma unroll
        for (int mt = 0; mt < 4; mt++) {
            C[mt][0] = 0.f; C[mt][1] = 0.f; C[mt][2] = 0.f; C[mt][3] = 0.f;
        }
#pragma unroll
        for (int kc = 0; kc < 8; kc++) {
#pragma unroll
            for (int mt = 0; mt < 4; mt++)
                mma16816(C[mt], A[mt][kc], b[kc][0], b[kc][1]);
        }

        if ((l & 3) == 0) {
#pragma unroll
            for (int mt = 0; mt < 4; mt++) {
                *(float2*)&preW[w][mt][strow][0]     = make_float2(C[mt][0], C[mt][1]);
                *(float2*)&preW[w][mt][strow + 8][0] = make_float2(C[mt][2], C[mt][3]);
            }
        }
        __syncwarp();

        float iv = siga (gi + preW[w][0][ul][p]);
        float fv = siga (gf + preW[w][1][ul][p]);
        float gv = tanha(gg + preW[w][2][ul][p]);
        float ov = siga (go + preW[w][3][ul][p]);
        c = fv * c + iv * gv;
        hval = ov * tanha(c);
        hN[cb ^ 1][p][u] = __float2half(hval);

        gi = ni; gf = nf; gg = ng; go = no_;
        gp = gn;
        __syncthreads();
    }
    g_ctx[pathg * 256 + dir * 128 + u] = hval;
}

// ---------------- attention --------------------------------------------------
__global__ void __launch_bounds__(256) att1_kernel(const float* __restrict__ d1b,
                                                   const float* __restrict__ d2w,
                                                   const float* __restrict__ d2b) {
    __shared__ float cat[512];
    __shared__ float red[256];
    int p = blockIdx.x, tid = threadIdx.x;
    cat[tid]       = g_ctx[p * 256 + tid];
    cat[256 + tid] = g_u[tid];
    __syncthreads();
    float acc = d1b[tid];
#pragma unroll 8
    for (int k = 0; k < 512; k++) acc += cat[k] * g_d1wT[k * 256 + tid];
    red[tid] = tanh_(acc) * d2w[tid];
    __syncthreads();
    for (int s = 128; s > 0; s >>= 1) {
        if (tid < s) red[tid] += red[tid + s];
        __syncthreads();
    }
    if (tid == 0) g_score[p] = red[0] + d2b[0];
}

__global__ void __launch_bounds__(256) att2_kernel(const float* __restrict__ d1b,
                                                   const float* __restrict__ d2w,
                                                   const float* __restrict__ d2b,
                                                   float* __restrict__ out, int last) {
    __shared__ float al[128];
    __shared__ float red[128];
    __shared__ float cat[512];
    int tid = threadIdx.x;
    cat[tid] = g_u[tid];
    if (tid < 128) red[tid] = g_score[tid];
    __syncthreads();
    for (int s = 64; s > 0; s >>= 1) {
        if (tid < s) red[tid] = fmaxf(red[tid], red[tid + s]);
        __syncthreads();
    }
    float m = red[0];
    __syncthreads();
    if (tid < 128) { float e = __expf(g_score[tid] - m); al[tid] = e; red[tid] = e; }
    __syncthreads();
    for (int s = 64; s > 0; s >>= 1) {
        if (tid < s) red[tid] += red[tid + s];
        __syncthreads();
    }
    float inv = __fdividef(1.f, red[0]);
    float o = 0.f;
#pragma unroll 8
    for (int p = 0; p < 128; p++) o += al[p] * g_ctx[p * 256 + tid];
    cat[256 + tid] = o * inv;
    __syncthreads();
    float acc = d1b[tid];
#pragma unroll 8
    for (int k = 0; k < 512; k++) acc += cat[k] * g_d1wT[k * 256 + tid];
    __syncthreads();
    if (!last) {
        g_u[tid] = acc;
    } else {
        cat[tid] = fmaxf(acc, 0.f) * d2w[tid];
        __syncthreads();
        for (int s = 128; s > 0; s >>= 1) {
            if (tid < s) cat[tid] += cat[tid + s];
            __syncthreads();
        }
        if (tid == 0) out[0] = __fdividef(1.f, 1.f + __expf(-(cat[0] + d2b[0])));
    }
}

// ---------------- launch ------------------------------------------------------
extern "C" void kernel_launch(void* const* d_in, const int* in_sizes, int n_in,
                              void* d_out, int out_size) {
    const int*   path   = (const int*)  d_in[0];
    const int*   query  = (const int*)  d_in[1];
    const float* embA   = (const float*)d_in[2];
    const float* embB   = (const float*)d_in[3];
    const float* conv_w = (const float*)d_in[4];
    const float* conv_b = (const float*)d_in[5];
    const float* wihf   = (const float*)d_in[6];
    const float* whhf   = (const float*)d_in[7];
    const float* bihf   = (const float*)d_in[8];
    const float* bhhf   = (const float*)d_in[9];
    const float* wihb   = (const float*)d_in[10];
    const float* whhb   = (const float*)d_in[11];
    const float* bihb   = (const float*)d_in[12];
    const float* bhhb   = (const float*)d_in[13];
    const float* d1w    = (const float*)d_in[14];
    const float* d1b    = (const float*)d_in[15];
    const float* d2w    = (const float*)d_in[16];
    const float* d2b    = (const float*)d_in[17];
    float* out = (float*)d_out;

    const int conv_smem = (132 * WROW + 128 * SROW) * 2;   // 104512 B
    const int gemm_smem = 3 * 128 * SROW * 2;              // 104448 B (Bs + 2xAs)
    cudaFuncSetAttribute(gemm_kernel, cudaFuncAttributeMaxDynamicSharedMemorySize, gemm_smem);
    cudaFuncSetAttribute(convgemm_kernel, cudaFuncAttributeMaxDynamicSharedMemorySize, conv_smem);

    setup_kernel<<<PREP_BLKS + 1, 256>>>(query, embB, conv_w, d1w,
                                         wihf, wihb, bihf, bhhf, bihb, bhhb);
    convgemm_kernel<<<510, 256, conv_smem>>>(path, embA, conv_b);
    pool_kernel<<<(Pn * Tn * 64 + 255) / 256, 256>>>();
    gemm_kernel<<<dim3(8, 64), 256, gemm_smem>>>();
    lstm_kernel<<<128, 256>>>(whhf, whhb);
    att1_kernel<<<128, 256>>>(d1b, d2w, d2b);
    att2_kernel<<<1, 256>>>(d1b, d2w, d2b, out, 0);
    att1_kernel<<<128, 256>>>(d1b, d2w, d2b);
    att2_kernel<<<1, 256>>>(d1b, d2w, d2b, out, 1);
}